// round 12
// baseline (speedup 1.0000x reference)
#include <cuda_runtime.h>
#include <cuda_fp16.h>
#include <math.h>
#include <stdint.h>

// Problem constants
#define Bn 2
#define Sn 1024
#define Dn 1024
#define NHn 16
#define HDn 64
#define En 8
#define HIDn 4096
#define Tn (Bn*Sn)          // 2048 tokens
#define MAXROWS 5248        // >= 4096 assignments + 8*127 padding, mult of 128

// ---------------- scratch (static device globals; no allocation) -------------
static __device__ __half g_XNh [Tn*Dn];
static __device__ float  g_Vb  [Tn*Dn];
static __device__ __half g_Qh  [Tn*Dn];
static __device__ __half g_Kh  [Tn*Dn];
static __device__ __half g_Vt  [(size_t)Bn*NHn*HDn*Sn];
static __device__ __half g_ATTh[Tn*Dn];
static __device__ float  g_Hb  [Tn*Dn];
static __device__ float  g_XN2 [Tn*Dn];
static __device__ __half g_XN2h[Tn*Dn];
static __device__ __half g_Hh  [(size_t)MAXROWS*HIDn];
// fp16 weights
static __device__ __half g_Wqh[Dn*Dn];
static __device__ __half g_Wkh[Dn*Dn];
static __device__ __half g_Wvh[Dn*Dn];
static __device__ __half g_Woh[Dn*Dn];
static __device__ __half g_Wgeh[(size_t)En*HIDn*Dn];
static __device__ __half g_Wueh[(size_t)En*HIDn*Dn];
static __device__ __half g_Wdeh[(size_t)En*Dn*HIDn];
// routing
static __device__ int   g_cnt[En];
static __device__ int   g_cursor[En];
static __device__ int   g_rowtok[MAXROWS];
static __device__ int   g_rowexp[MAXROWS];
static __device__ float g_rowgate[MAXROWS];
static __device__ int   g_totalrows;
static __device__ float g_gsum[En];
static __device__ float g_psum[En];
static __device__ int   g_expid[Tn*2];
static __device__ float g_gateval[Tn*2];

// ======================= PTX helpers =========================================
static __device__ __forceinline__ uint32_t smem_u32_(const void* p){
    uint32_t a;
    asm("{ .reg .u64 t; cvta.to.shared.u64 t, %1; cvt.u32.u64 %0, t; }"
        : "=r"(a) : "l"(p));
    return a;
}

#define LDSM_X4(r0,r1,r2,r3,addr) \
    asm volatile("ldmatrix.sync.aligned.m8n8.x4.shared.b16 {%0,%1,%2,%3}, [%4];" \
        : "=r"(r0),"=r"(r1),"=r"(r2),"=r"(r3) : "r"(addr))

#define MMA16816(c,a,b) \
    asm volatile("mma.sync.aligned.m16n8k16.row.col.f32.f16.f16.f32 " \
        "{%0,%1,%2,%3}, {%4,%5,%6,%7}, {%8,%9}, {%0,%1,%2,%3};" \
        : "+f"((c)[0]),"+f"((c)[1]),"+f"((c)[2]),"+f"((c)[3]) \
        : "r"((a)[0]),"r"((a)[1]),"r"((a)[2]),"r"((a)[3]), \
          "r"((b)[0]),"r"((b)[1]))

#define CP_COMMIT() asm volatile("cp.async.commit_group;" ::: "memory")
#define CP_WAIT(N)  asm volatile("cp.async.wait_group %0;" :: "n"(N) : "memory")

static __device__ __forceinline__ void cp16_(uint32_t dst, const void* src, int srcsize){
    asm volatile("cp.async.cg.shared.global [%0], [%1], 16, %2;"
        :: "r"(dst), "l"((unsigned long long)__cvta_generic_to_global(src)),
           "r"(srcsize) : "memory");
}

// ============================== small kernels ================================
__global__ void k_reset() {
    int i = threadIdx.x;
    if (i < En) { g_cnt[i] = 0; g_gsum[i] = 0.f; g_psum[i] = 0.f; }
}

static __device__ __forceinline__ void f2h_one_(const float4* s, uint2* d, int i){
    float4 v = s[i];
    __half2 h0 = __floats2half2_rn(v.x, v.y);
    __half2 h1 = __floats2half2_rn(v.z, v.w);
    uint2 o;
    o.x = *reinterpret_cast<uint32_t*>(&h0);
    o.y = *reinterpret_cast<uint32_t*>(&h1);
    d[i] = o;
}

__global__ void k_f2h2(const float4* __restrict__ s0, const float4* __restrict__ s1,
                       uint2* __restrict__ d0, uint2* __restrict__ d1, int n4){
    int i = blockIdx.x*blockDim.x + threadIdx.x;
    if (i >= n4) return;
    if (blockIdx.y == 0) f2h_one_(s0, d0, i);
    else                 f2h_one_(s1, d1, i);
}

__global__ void k_f2h4(const float4* __restrict__ s0, const float4* __restrict__ s1,
                       const float4* __restrict__ s2p, const float4* __restrict__ s3,
                       uint2* __restrict__ d0, uint2* __restrict__ d1,
                       uint2* __restrict__ d2, uint2* __restrict__ d3, int n4){
    int i = blockIdx.x*blockDim.x + threadIdx.x;
    if (i >= n4) return;
    switch (blockIdx.y){
        case 0: f2h_one_(s0, d0, i); break;
        case 1: f2h_one_(s1, d1, i); break;
        case 2: f2h_one_(s2p, d2, i); break;
        default: f2h_one_(s3, d3, i); break;
    }
}

__global__ void k_f2h(const float4* __restrict__ s, uint2* __restrict__ d, int n4){
    int i = blockIdx.x*blockDim.x + threadIdx.x;
    if (i >= n4) return;
    f2h_one_(s, d, i);
}

__global__ void k_rmsnorm(const float* __restrict__ x, const float* __restrict__ w,
                          float* __restrict__ y, __half* __restrict__ yh) {
    int t = blockIdx.x;
    const float* xr = x + (size_t)t * Dn;
    int base = threadIdx.x * 4;
    float4 xv = *(const float4*)(xr + base);
    float ss = xv.x*xv.x + xv.y*xv.y + xv.z*xv.z + xv.w*xv.w;
    #pragma unroll
    for (int o = 16; o; o >>= 1) ss += __shfl_xor_sync(0xffffffffu, ss, o);
    __shared__ float ws[8];
    if ((threadIdx.x & 31) == 0) ws[threadIdx.x >> 5] = ss;
    __syncthreads();
    float tot = ws[0]+ws[1]+ws[2]+ws[3]+ws[4]+ws[5]+ws[6]+ws[7];
    float sc = rsqrtf(tot * (1.f/(float)Dn) + 1e-6f);
    float4 wv = *(const float4*)(w + base);
    float4 o4;
    o4.x = wv.x*xv.x*sc; o4.y = wv.y*xv.y*sc;
    o4.z = wv.z*xv.z*sc; o4.w = wv.w*xv.w*sc;
    if (y) *(float4*)(y + (size_t)t*Dn + base) = o4;
    __half2 h0 = __floats2half2_rn(o4.x, o4.y);
    __half2 h1 = __floats2half2_rn(o4.z, o4.w);
    uint2 ho;
    ho.x = *reinterpret_cast<uint32_t*>(&h0);
    ho.y = *reinterpret_cast<uint32_t*>(&h1);
    *(uint2*)(yh + (size_t)t*Dn + base) = ho;
}

// ===================== mma.sync GEMM (HMMA tensor path) ======================
#define EPI_PLAIN 0
#define EPI_RESID 1
#define EPI_DOWN  2
#define EPI_HALF  3
#define EPI_ROPE  4
#define GEMM_SMEM (3*32768)

template<int NITER, int EPI, bool GATHER, bool ESEL, bool ZSPLIT=false>
__global__ __launch_bounds__(256)
void k_gemm(const __half* __restrict__ A0, int lda,
            const __half* __restrict__ B0, const __half* __restrict__ B1,
            const __half* __restrict__ B2,
            long bstride, int ldb,
            void* __restrict__ C0v, void* __restrict__ C1v, void* __restrict__ C2v,
            int ldc,
            const float* __restrict__ resid, float* __restrict__ Cdual)
{
    constexpr int S = 3;
    int mt = blockIdx.y, nt = blockIdx.x;
    if (ESEL && mt*128 >= g_totalrows) return;
    const __half* Bh = ZSPLIT ? B0
        : ((blockIdx.z==0) ? B0 : ((blockIdx.z==1) ? B1 : B2));
    void* Cv = ZSPLIT ? C0v
        : ((blockIdx.z==0) ? C0v : ((blockIdx.z==1) ? C1v : C2v));
    if (ESEL) Bh += (long)g_rowexp[mt*128] * bstride;
    long koff = ZSPLIT ? (long)blockIdx.z * (NITER*64) : 0;

    extern __shared__ __align__(128) char sm_[];
    uint32_t sbase = smem_u32_(sm_);

    int tid = threadIdx.x, lane = tid & 31, wid = tid >> 5;
    int warp_m = wid & 3, warp_n = wid >> 2;

    int lrow = tid >> 1;
    int lc0  = (tid & 1) * 4;
    const __half* asrc;
    bool avalid = true;
    if (GATHER){
        int tok = g_rowtok[mt*128 + lrow];
        avalid = (tok >= 0);
        asrc = A0 + (avalid ? (size_t)tok * lda : 0);
    } else {
        asrc = A0 + (size_t)(mt*128 + lrow) * lda;
    }
    asrc += koff;
    const __half* bsrc = Bh + (size_t)(nt*128 + lrow) * ldb + koff;
    int asz = avalid ? 16 : 0;
    uint32_t arow_s = sbase + lrow*128;
    uint32_t brow_s = arow_s + 16384;

    auto stg = [&](int it){
        int stage = it % S;
        uint32_t so = (uint32_t)stage * 32768u;
        const char* ag = (const char*)(asrc + it*64);
        const char* bg = (const char*)(bsrc + it*64);
        #pragma unroll
        for (int i = 0; i < 4; i++){
            int c = lc0 + i;
            uint32_t sw = (uint32_t)((c ^ (lrow & 7)) * 16);
            cp16_(arow_s + so + sw, ag + c*16, asz);
            cp16_(brow_s + so + sw, bg + c*16, 16);
        }
    };

    float acc[2][8][4];
    #pragma unroll
    for (int i=0;i<2;i++)
        #pragma unroll
        for (int j=0;j<8;j++)
            #pragma unroll
            for (int k=0;k<4;k++) acc[i][j][k]=0.f;

    #pragma unroll
    for (int it = 0; it < S-1; it++){ stg(it); CP_COMMIT(); }

    int a_rlo = (lane & 15);
    int a_chk = (lane >> 4);
    int b_rlo = (lane & 7) + ((lane & 16) ? 8 : 0);
    int b_chk = (lane >> 3) & 1;

    for (int it = 0; it < NITER; it++){
        CP_WAIT(S-2);
        __syncthreads();
        if (it + S-1 < NITER) stg(it + S-1);
        CP_COMMIT();

        uint32_t so = (uint32_t)(it % S) * 32768u;
        uint32_t abase = sbase + so;
        uint32_t bbase = abase + 16384;

        #pragma unroll
        for (int ks = 0; ks < 4; ks++){
            uint32_t a[2][4];
            #pragma unroll
            for (int mtile = 0; mtile < 2; mtile++){
                int row = warp_m*32 + mtile*16 + a_rlo;
                int chunk = 2*ks + a_chk;
                uint32_t addr = abase + row*128 + ((chunk ^ (row & 7)) * 16);
                LDSM_X4(a[mtile][0], a[mtile][1], a[mtile][2], a[mtile][3], addr);
            }
            uint32_t b[8][2];
            #pragma unroll
            for (int n2 = 0; n2 < 4; n2++){
                int row = warp_n*64 + n2*16 + b_rlo;
                int chunk = 2*ks + b_chk;
                uint32_t addr = bbase + row*128 + ((chunk ^ (row & 7)) * 16);
                uint32_t r0,r1,r2,r3;
                LDSM_X4(r0, r1, r2, r3, addr);
                b[2*n2][0]=r0; b[2*n2][1]=r1;
                b[2*n2+1][0]=r2; b[2*n2+1][1]=r3;
            }
            #pragma unroll
            for (int mtile = 0; mtile < 2; mtile++)
                #pragma unroll
                for (int n8 = 0; n8 < 8; n8++)
                    MMA16816(acc[mtile][n8], a[mtile], b[n8]);
        }
        __syncthreads();
    }

    // ---- epilogue ----
    int m0 = mt*128 + warp_m*32;
    int n0 = nt*128 + warp_n*64;
    int gq = lane >> 2, tq = lane & 3;
    #pragma unroll
    for (int mtile = 0; mtile < 2; mtile++){
        int r_lo = m0 + mtile*16 + gq;
        int r_hi = r_lo + 8;
        if (EPI == EPI_DOWN){
            float* C = (float*)Cv;
            int tok_lo = g_rowtok[r_lo], tok_hi = g_rowtok[r_hi];
            float gl = g_rowgate[r_lo], gh = g_rowgate[r_hi];
            #pragma unroll
            for (int n8 = 0; n8 < 8; n8++){
                int col = n0 + n8*8 + tq*2;
                if (tok_lo >= 0){
                    size_t o = (size_t)tok_lo*ldc + col;
                    atomicAdd(&C[o],   gl*acc[mtile][n8][0]);
                    atomicAdd(&C[o+1], gl*acc[mtile][n8][1]);
                }
                if (tok_hi >= 0){
                    size_t o = (size_t)tok_hi*ldc + col;
                    atomicAdd(&C[o],   gh*acc[mtile][n8][2]);
                    atomicAdd(&C[o+1], gh*acc[mtile][n8][3]);
                }
            }
        } else if (EPI == EPI_RESID){
            float* C = (float*)Cv;
            #pragma unroll
            for (int n8 = 0; n8 < 8; n8++){
                int col = n0 + n8*8 + tq*2;
                size_t o_lo = (size_t)r_lo*ldc + col;
                size_t o_hi = (size_t)r_hi*ldc + col;
                float2 rv0 = *(const float2*)(resid + o_lo);
                float2 rv1 = *(const float2*)(resid + o_hi);
                float2 v0, v1;
                v0.x = acc[mtile][n8][0] + rv0.x;
                v0.y = acc[mtile][n8][1] + rv0.y;
                v1.x = acc[mtile][n8][2] + rv1.x;
                v1.y = acc[mtile][n8][3] + rv1.y;
                *(float2*)(C + o_lo) = v0;
                *(float2*)(C + o_hi) = v1;
                *(float2*)(Cdual + o_lo) = v0;
                *(float2*)(Cdual + o_hi) = v1;
            }
        } else if (EPI == EPI_HALF){
            __half* Ch = (__half*)Cv;
            #pragma unroll
            for (int n8 = 0; n8 < 8; n8++){
                int col = n0 + n8*8 + tq*2;
                __half2 v0 = __floats2half2_rn(acc[mtile][n8][0], acc[mtile][n8][1]);
                __half2 v1 = __floats2half2_rn(acc[mtile][n8][2], acc[mtile][n8][3]);
                *(__half2*)(Ch + (size_t)r_lo*ldc + col) = v0;
                *(__half2*)(Ch + (size_t)r_hi*ldc + col) = v1;
            }
        } else if (EPI == EPI_ROPE){
            if (blockIdx.z == 2){
                float* C = (float*)Cv;
                #pragma unroll
                for (int n8 = 0; n8 < 8; n8++){
                    int col = n0 + n8*8 + tq*2;
                    float2 v0, v1;
                    v0.x = acc[mtile][n8][0]; v0.y = acc[mtile][n8][1];
                    v1.x = acc[mtile][n8][2]; v1.y = acc[mtile][n8][3];
                    *(float2*)(C + (size_t)r_lo*ldc + col) = v0;
                    *(float2*)(C + (size_t)r_hi*ldc + col) = v1;
                }
            } else {
                __half* Ch = (__half*)Cv;
                int s_lo = r_lo & (Sn-1);
                int s_hi = r_hi & (Sn-1);
                #pragma unroll
                for (int n8 = 0; n8 < 4; n8++){
                    int col = n0 + n8*8 + tq*2;
                    int i0 = col & 63;                      // < 32
                    float inv0 = powf(10000.f, (float)(-2*i0)   * (1.f/64.f));
                    float inv1 = powf(10000.f, (float)(-2*(i0+1)) * (1.f/64.f));
                    float c0l,s0l,c1l,s1l,c0h,s0h,c1h,s1h;
                    sincosf((float)s_lo*inv0, &s0l, &c0l);
                    sincosf((float)s_lo*inv1, &s1l, &c1l);
                    sincosf((float)s_hi*inv0, &s0h, &c0h);
                    sincosf((float)s_hi*inv1, &s1h, &c1h);
                    float a0 = acc[mtile][n8][0],   a1 = acc[mtile][n8][1];
                    float b0 = acc[mtile][n8+4][0], b1 = acc[mtile][n8+4][1];
                    float a2 = acc[mtile][n8][2],   a3 = acc[mtile][n8][3];
                    float b2 = acc[mtile][n8+4][2], b3 = acc[mtile][n8+4][3];
                    __half2 lo_a = __floats2half2_rn(a0*c0l - b0*s0l, a1*c1l - b1*s1l);
                    __half2 lo_b = __floats2half2_rn(b0*c0l + a0*s0l, b1*c1l + a1*s1l);
                    __half2 hi_a = __floats2half2_rn(a2*c0h - b2*s0h, a3*c1h - b3*s1h);
                    __half2 hi_b = __floats2half2_rn(b2*c0h + a2*s0h, b3*c1h + a3*s1h);
                    *(__half2*)(Ch + (size_t)r_lo*ldc + col)      = lo_a;
                    *(__half2*)(Ch + (size_t)r_lo*ldc + col + 32) = lo_b;
                    *(__half2*)(Ch + (size_t)r_hi*ldc + col)      = hi_a;
                    *(__half2*)(Ch + (size_t)r_hi*ldc + col + 32) = hi_b;
                }
            }
        } else {
            float* C = (float*)Cv;
            #pragma unroll
            for (int n8 = 0; n8 < 8; n8++){
                int col = n0 + n8*8 + tq*2;
                float2 v0, v1;
                v0.x = acc[mtile][n8][0]; v0.y = acc[mtile][n8][1];
                v1.x = acc[mtile][n8][2]; v1.y = acc[mtile][n8][3];
                *(float2*)(C + (size_t)r_lo*ldc + col) = v0;
                *(float2*)(C + (size_t)r_hi*ldc + col) = v1;
            }
        }
    }
}

// ============== fused gate+up+SwiGLU GEMM (dual-B, writes Hh) ================
// Hh[row][col] = silu(A@Wg^T) * (A@Wu^T), fp32 accum, fp16 out.
// smem per stage: A 16KB + Bg 16KB + Bu 16KB = 48KB; 3 stages = 144KB.
#define SWIGLU_SMEM (3*49152)

__global__ __launch_bounds__(256)
void k_gemm_swiglu(const __half* __restrict__ A0, int lda,
                   const __half* __restrict__ Bg0, const __half* __restrict__ Bu0,
                   long bstride, int ldb,
                   __half* __restrict__ C, int ldc)
{
    constexpr int S = 3;
    constexpr int NITER = 16;
    int mt = blockIdx.y, nt = blockIdx.x;
    if (mt*128 >= g_totalrows) return;
    long eoff = (long)g_rowexp[mt*128] * bstride;
    const __half* Bg = Bg0 + eoff;
    const __half* Bu = Bu0 + eoff;

    extern __shared__ __align__(128) char sm_[];
    uint32_t sbase = smem_u32_(sm_);

    int tid = threadIdx.x, lane = tid & 31, wid = tid >> 5;
    int warp_m = wid & 3, warp_n = wid >> 2;

    int lrow = tid >> 1;
    int lc0  = (tid & 1) * 4;
    int tok = g_rowtok[mt*128 + lrow];
    bool avalid = (tok >= 0);
    const __half* asrc = A0 + (avalid ? (size_t)tok * lda : 0);
    const __half* bgsrc = Bg + (size_t)(nt*128 + lrow) * ldb;
    const __half* busrc = Bu + (size_t)(nt*128 + lrow) * ldb;
    int asz = avalid ? 16 : 0;
    uint32_t arow_s = sbase + lrow*128;

    auto stg = [&](int it){
        uint32_t so = (uint32_t)(it % S) * 49152u;
        const char* ag = (const char*)(asrc + it*64);
        const char* gg = (const char*)(bgsrc + it*64);
        const char* ug = (const char*)(busrc + it*64);
        #pragma unroll
        for (int i = 0; i < 4; i++){
            int c = lc0 + i;
            uint32_t sw = (uint32_t)((c ^ (lrow & 7)) * 16);
            cp16_(arow_s + so + sw,          ag + c*16, asz);
            cp16_(arow_s + so + 16384u + sw, gg + c*16, 16);
            cp16_(arow_s + so + 32768u + sw, ug + c*16, 16);
        }
    };

    float accg[2][8][4], accu[2][8][4];
    #pragma unroll
    for (int i=0;i<2;i++)
        #pragma unroll
        for (int j=0;j<8;j++)
            #pragma unroll
            for (int k=0;k<4;k++){ accg[i][j][k]=0.f; accu[i][j][k]=0.f; }

    #pragma unroll
    for (int it = 0; it < S-1; it++){ stg(it); CP_COMMIT(); }

    int a_rlo = (lane & 15);
    int a_chk = (lane >> 4);
    int b_rlo = (lane & 7) + ((lane & 16) ? 8 : 0);
    int b_chk = (lane >> 3) & 1;

    for (int it = 0; it < NITER; it++){
        CP_WAIT(S-2);
        __syncthreads();
        if (it + S-1 < NITER) stg(it + S-1);
        CP_COMMIT();

        uint32_t so = (uint32_t)(it % S) * 49152u;
        uint32_t abase = sbase + so;
        uint32_t gbase = abase + 16384u;
        uint32_t ubase = abase + 32768u;

        #pragma unroll
        for (int ks = 0; ks < 4; ks++){
            uint32_t a[2][4];
            #pragma unroll
            for (int mtile = 0; mtile < 2; mtile++){
                int row = warp_m*32 + mtile*16 + a_rlo;
                int chunk = 2*ks + a_chk;
                uint32_t addr = abase + row*128 + ((chunk ^ (row & 7)) * 16);
                LDSM_X4(a[mtile][0], a[mtile][1], a[mtile][2], a[mtile][3], addr);
            }
            int brow_base = warp_n*64;
            int chunk = 2*ks + b_chk;
            #pragma unroll
            for (int n2 = 0; n2 < 4; n2++){
                int row = brow_base + n2*16 + b_rlo;
                uint32_t sw = (uint32_t)(row*128 + ((chunk ^ (row & 7)) * 16));
                uint32_t r0,r1,r2,r3;
                LDSM_X4(r0, r1, r2, r3, gbase + sw);
                uint32_t bg_[2][2];
                bg_[0][0]=r0; bg_[0][1]=r1; bg_[1][0]=r2; bg_[1][1]=r3;
                #pragma unroll
                for (int mtile = 0; mtile < 2; mtile++){
                    MMA16816(accg[mtile][2*n2],   a[mtile], bg_[0]);
                    MMA16816(accg[mtile][2*n2+1], a[mtile], bg_[1]);
                }
                LDSM_X4(r0, r1, r2, r3, ubase + sw);
                uint32_t bu_[2][2];
                bu_[0][0]=r0; bu_[0][1]=r1; bu_[1][0]=r2; bu_[1][1]=r3;
                #pragma unroll
                for (int mtile = 0; mtile < 2; mtile++){
                    MMA16816(accu[mtile][2*n2],   a[mtile], bu_[0]);
                    MMA16816(accu[mtile][2*n2+1], a[mtile], bu_[1]);
                }
            }
        }
        __syncthreads();
    }

    // ---- epilogue: silu(g)*u -> fp16 ----
    int m0 = mt*128 + warp_m*32;
    int n0 = nt*128 + warp_n*64;
    int gq = lane >> 2, tq = lane & 3;
    #pragma unroll
    for (int mtile = 0; mtile < 2; mtile++){
        int r_lo = m0 + mtile*16 + gq;
        int r_hi = r_lo + 8;
        #pragma unroll
        for (int n8 = 0; n8 < 8; n8++){
            int col = n0 + n8*8 + tq*2;
            float g0 = accg[mtile][n8][0], g1 = accg[mtile][n8][1];
            float g2 = accg[mtile][n8][2], g3 = accg[mtile][n8][3];
            float h0 = (g0 / (1.f + __expf(-g0))) * accu[mtile][n8][0];
            float h1 = (g1 / (1.f + __expf(-g1))) * accu[mtile][n8][1];
            float h2 = (g2 / (1.f + __expf(-g2))) * accu[mtile][n8][2];
            float h3 = (g3 / (1.f + __expf(-g3))) * accu[mtile][n8][3];
            __half2 v0 = __floats2half2_rn(h0, h1);
            __half2 v1 = __floats2half2_rn(h2, h3);
            *(__half2*)(C + (size_t)r_lo*ldc + col) = v0;
            *(__half2*)(C + (size_t)r_hi*ldc + col) = v1;
        }
    }
}

// ============ V transpose: fp32 [t][h*64+d] -> fp16 Vt[bh][d][s] =============
__global__ void k_vtrans(const float* __restrict__ V, __half* __restrict__ Vt)
{
    __shared__ float ts[64][65];
    int bh = blockIdx.x, st = blockIdx.y;
    int b = bh >> 4, h = bh & 15;
    int tid = threadIdx.x;                 // 128 threads
    int row = tid >> 1, c0 = (tid & 1) * 32;
    const float4* src = (const float4*)(V + ((size_t)(b*Sn + st*64 + row))*Dn
                                          + h*HDn + c0);
    #pragma unroll
    for (int i = 0; i < 8; i++){
        float4 v = src[i];
        ts[row][c0 + 4*i + 0] = v.x;
        ts[row][c0 + 4*i + 1] = v.y;
        ts[row][c0 + 4*i + 2] = v.z;
        ts[row][c0 + 4*i + 3] = v.w;
    }
    __syncthreads();
    __half* dst = Vt + ((size_t)bh*HDn + row)*Sn + st*64 + c0;
    #pragma unroll
    for (int i = 0; i < 32; i += 2){
        __half2 hv = __floats2half2_rn(ts[c0+i][row], ts[c0+i+1][row]);
        *(__half2*)(dst + i) = hv;
    }
}

// ================= HMMA flash attention (m16n8k16) ===========================
__global__ __launch_bounds__(128)
void k_attn_mma(const __half* __restrict__ Qh, const __half* __restrict__ Kh,
                const __half* __restrict__ Vt, __half* __restrict__ O)
{
    __shared__ __align__(128) char sm[3*8192];
    uint32_t qs = smem_u32_(sm);
    uint32_t ks = qs + 8192;
    uint32_t vs = qs + 16384;

    int bh = blockIdx.x;
    int qt = blockIdx.y;
    int b = bh >> 4, h = bh & 15;
    int tid = threadIdx.x, lane = tid & 31, wid = tid >> 5;
    int q0 = qt*64;

    int srow = tid >> 1, sc0 = (tid & 1) * 4;
    int gq = lane >> 2, tq = lane & 3;
    int a_rlo = lane & 15, a_chk = lane >> 4;
    int b_rlo = (lane & 7) + ((lane & 16) ? 8 : 0);
    int b_chk = (lane >> 3) & 1;

    {
        const uint4* src = (const uint4*)(Qh + ((size_t)(b*Sn + q0 + srow))*Dn + h*HDn);
        #pragma unroll
        for (int i = 0; i < 4; i++){
            int c = sc0 + i;
            *(uint4*)(sm + srow*128 + ((c ^ (srow & 7)) * 16)) = src[c];
        }
    }
    __syncthreads();

    uint32_t qa[4][4];
    #pragma unroll
    for (int kc = 0; kc < 4; kc++){
        int row = wid*16 + a_rlo;
        int chunk = kc*2 + a_chk;
        uint32_t addr = qs + row*128 + ((chunk ^ (row & 7)) * 16);
        LDSM_X4(qa[kc][0], qa[kc][1], qa[kc][2], qa[kc][3], addr);
    }

    float o_[8][4];
    #pragma unroll
    for (int j=0;j<8;j++)
        #pragma unroll
        for (int k=0;k<4;k++) o_[j][k]=0.f;
    float m_lo = -1e30f, m_hi = -1e30f, l_lo = 0.f, l_hi = 0.f;

    for (int kt = 0; kt <= qt; kt++){
        {
            const uint4* ksrc = (const uint4*)(Kh + ((size_t)(b*Sn + kt*64 + srow))*Dn + h*HDn);
            const uint4* vsrc = (const uint4*)(Vt + ((size_t)bh*HDn + srow)*Sn + kt*64);
            #pragma unroll
            for (int i = 0; i < 4; i++){
                int c = sc0 + i;
                uint32_t sw = (uint32_t)((c ^ (srow & 7)) * 16);
                *(uint4*)(sm + 8192  + srow*128 + sw) = ksrc[c];
                *(uint4*)(sm + 16384 + srow*128 + sw) = vsrc[c];
            }
        }
        __syncthreads();

        float s_[8][4];
        #pragma unroll
        for (int j=0;j<8;j++)
            #pragma unroll
            for (int k=0;k<4;k++) s_[j][k]=0.f;
        #pragma unroll
        for (int kc = 0; kc < 4; kc++){
            uint32_t kb[8][2];
            #pragma unroll
            for (int n2 = 0; n2 < 4; n2++){
                int row = n2*16 + b_rlo;
                int chunk = kc*2 + b_chk;
                uint32_t addr = ks + row*128 + ((chunk ^ (row & 7)) * 16);
                uint32_t r0,r1,r2,r3;
                LDSM_X4(r0, r1, r2, r3, addr);
                kb[2*n2][0]=r0; kb[2*n2][1]=r1;
                kb[2*n2+1][0]=r2; kb[2*n2+1][1]=r3;
            }
            #pragma unroll
            for (int j = 0; j < 8; j++)
                MMA16816(s_[j], qa[kc], kb[j]);
        }

        int row_lo = q0 + wid*16 + gq;
        int row_hi = row_lo + 8;
        #pragma unroll
        for (int j = 0; j < 8; j++){
            int c0 = kt*64 + j*8 + tq*2;
            int c1 = c0 + 1;
            s_[j][0] = (c0 <= row_lo) ? s_[j][0]*0.125f : -1e30f;
            s_[j][1] = (c1 <= row_lo) ? s_[j][1]*0.125f : -1e30f;
            s_[j][2] = (c0 <= row_hi) ? s_[j][2]*0.125f : -1e30f;
            s_[j][3] = (c1 <= row_hi) ? s_[j][3]*0.125f : -1e30f;
        }

        float tm_lo = -1e30f, tm_hi = -1e30f;
        #pragma unroll
        for (int j = 0; j < 8; j++){
            tm_lo = fmaxf(tm_lo, fmaxf(s_[j][0], s_[j][1]));
            tm_hi = fmaxf(tm_hi, fmaxf(s_[j][2], s_[j][3]));
        }
        tm_lo = fmaxf(tm_lo, __shfl_xor_sync(0xffffffffu, tm_lo, 1));
        tm_lo = fmaxf(tm_lo, __shfl_xor_sync(0xffffffffu, tm_lo, 2));
        tm_hi = fmaxf(tm_hi, __shfl_xor_sync(0xffffffffu, tm_hi, 1));
        tm_hi = fmaxf(tm_hi, __shfl_xor_sync(0xffffffffu, tm_hi, 2));
        float mn_lo = fmaxf(m_lo, tm_lo);
        float mn_hi = fmaxf(m_hi, tm_hi);
        float corr_lo = __expf(m_lo - mn_lo);
        float corr_hi = __expf(m_hi - mn_hi);
        float rs_lo = 0.f, rs_hi = 0.f;
        #pragma unroll
        for (int j = 0; j < 8; j++){
            s_[j][0] = __expf(s_[j][0] - mn_lo);
            s_[j][1] = __expf(s_[j][1] - mn_lo);
            s_[j][2] = __expf(s_[j][2] - mn_hi);
            s_[j][3] = __expf(s_[j][3] - mn_hi);
            rs_lo += s_[j][0] + s_[j][1];
            rs_hi += s_[j][2] + s_[j][3];
        }
        rs_lo += __shfl_xor_sync(0xffffffffu, rs_lo, 1);
        rs_lo += __shfl_xor_sync(0xffffffffu, rs_lo, 2);
        rs_hi += __shfl_xor_sync(0xffffffffu, rs_hi, 1);
        rs_hi += __shfl_xor_sync(0xffffffffu, rs_hi, 2);
        l_lo = l_lo*corr_lo + rs_lo;
        l_hi = l_hi*corr_hi + rs_hi;
        m_lo = mn_lo; m_hi = mn_hi;
        #pragma unroll
        for (int j = 0; j < 8; j++){
            o_[j][0] *= corr_lo; o_[j][1] *= corr_lo;
            o_[j][2] *= corr_hi; o_[j][3] *= corr_hi;
        }

        uint32_t pa[4][4];
        #pragma unroll
        for (int kc = 0; kc < 4; kc++){
            __half2 h0 = __floats2half2_rn(s_[2*kc][0],   s_[2*kc][1]);
            __half2 h1 = __floats2half2_rn(s_[2*kc][2],   s_[2*kc][3]);
            __half2 h2 = __floats2half2_rn(s_[2*kc+1][0], s_[2*kc+1][1]);
            __half2 h3 = __floats2half2_rn(s_[2*kc+1][2], s_[2*kc+1][3]);
            pa[kc][0] = *reinterpret_cast<uint32_t*>(&h0);
            pa[kc][1] = *reinterpret_cast<uint32_t*>(&h1);
            pa[kc][2] = *reinterpret_cast<uint32_t*>(&h2);
            pa[kc][3] = *reinterpret_cast<uint32_t*>(&h3);
        }

        #pragma unroll
        for (int kc = 0; kc < 4; kc++){
            uint32_t vb[8][2];
            #pragma unroll
            for (int n2 = 0; n2 < 4; n2++){
                int row = n2*16 + b_rlo;
                int chunk = kc*2 + b_chk;
                uint32_t addr = vs + row*128 + ((chunk ^ (row & 7)) * 16);
                uint32_t r0,r1,r2,r3;
                LDSM_X4(r0, r1, r2, r3, addr);
                vb[2*n2][0]=r0; vb[2*n2][1]=r1;
                vb[2*n2+1][0]=r2; vb[2*n2+1][1]=r3;
            }
            #pragma unroll
            for (int j = 0; j < 8; j++)
                MMA16816(o_[j], pa[kc], vb[j]);
        }
        __syncthreads();
    }

    float inv_lo = 1.f/l_lo, inv_hi = 1.f/l_hi;
    int row_lo = q0 + wid*16 + gq;
    int row_hi = row_lo + 8;
    #pragma unroll
    for (int j = 0; j < 8; j++){
        int col = j*8 + tq*2;
        __half2 v0 = __floats2half2_rn(o_[j][0]*inv_lo, o_[j][1]*inv_lo);
        __half2 v1 = __floats2half2_rn(o_[j][2]*inv_hi, o_[j][3]*inv_hi);
        *(__half2*)(O + ((size_t)(b*Sn + row_lo))*Dn + h*HDn + col) = v0;
        *(__half2*)(O + ((size_t)(b*Sn + row_hi))*Dn + h*HDn + col) = v1;
    }
}

// =============================== gating / MoE ================================
__global__ void k_gate(const float* __restrict__ xn, const float* __restrict__ gw)
{
    int t = blockIdx.x;
    int w = threadIdx.x >> 5, lane = threadIdx.x & 31;
    const float* xr = xn + (size_t)t * Dn;
    const float* gr = gw + (size_t)w * Dn;
    float acc = 0.f;
    for (int d = lane; d < Dn; d += 32) acc = fmaf(xr[d], gr[d], acc);
    #pragma unroll
    for (int o=16;o;o>>=1) acc += __shfl_xor_sync(0xffffffffu, acc, o);
    __shared__ float lg[En];
    if (lane == 0) lg[w] = acc;
    __syncthreads();
    if (threadIdx.x == 0){
        int i1 = 0;
        for (int e=1;e<En;e++) if (lg[e] > lg[i1]) i1 = e;
        int i2 = -1;
        for (int e=0;e<En;e++){
            if (e == i1) continue;
            if (i2 < 0 || lg[e] > lg[i2]) i2 = e;
        }
        float l1 = lg[i1], l2 = lg[i2];
        float e2 = expf(l2 - l1);
        float inv = 1.f/(1.f + e2);
        float gv1 = inv, gv2 = e2*inv;
        g_expid[t*2]   = i1; g_expid[t*2+1]   = i2;
        g_gateval[t*2] = gv1; g_gateval[t*2+1] = gv2;
        atomicAdd(&g_cnt[i1], 1); atomicAdd(&g_cnt[i2], 1);
        atomicAdd(&g_gsum[i1], gv1); atomicAdd(&g_gsum[i2], gv2);
        float mx = lg[0];
        for (int e=1;e<En;e++) mx = fmaxf(mx, lg[e]);
        float pe[En]; float se = 0.f;
        for (int e=0;e<En;e++){ pe[e] = expf(lg[e]-mx); se += pe[e]; }
        float pinv = 1.f/se;
        for (int e=0;e<En;e++) atomicAdd(&g_psum[e], pe[e]*pinv);
    }
}

__global__ void k_offsets(float* __restrict__ out, int write_aux)
{
    __shared__ int soff[En+1];
    if (threadIdx.x == 0){
        int tot = 0;
        for (int e=0;e<En;e++){
            soff[e] = tot;
            g_cursor[e] = tot;
            tot += ((g_cnt[e] + 127) >> 7) << 7;
        }
        soff[En] = tot;
        g_totalrows = tot;
        if (write_aux){
            float sacc = 0.f;
            for (int e=0;e<En;e++) sacc += g_gsum[e]*g_psum[e];
            out[(size_t)Tn*Dn] = (float)En * sacc / ((float)Tn*(float)Tn);
        }
    }
    __syncthreads();
    int tot = soff[En];
    for (int r = threadIdx.x; r < tot; r += blockDim.x){
        int e = 0;
        while (e+1 < En && r >= soff[e+1]) e++;
        g_rowexp[r] = e;
        g_rowtok[r] = -1;
    }
}

__global__ void k_scatter()
{
    int t = blockIdx.x*blockDim.x + threadIdx.x;
    if (t >= Tn) return;
    #pragma unroll
    for (int k=0;k<2;k++){
        int e = g_expid[t*2+k];
        int pos = atomicAdd(&g_cursor[e], 1);
        g_rowtok[pos] = t;
        g_rowgate[pos] = g_gateval[t*2+k];
    }
}

// ---------------------------------------------------------------------------
extern "C" void kernel_launch(void* const* d_in, const int* in_sizes, int n_in,
                              void* d_out, int out_size)
{
    (void)in_sizes; (void)n_in;
    const float* x   = (const float*)d_in[0];
    const float* wq  = (const float*)d_in[1];
    const float* wk  = (const float*)d_in[2];
    const float* wv  = (const float*)d_in[3];
    const float* wo  = (const float*)d_in[4];
    const float* anw = (const float*)d_in[5];
    const float* fnw = (const float*)d_in[6];
    const float* gw  = (const float*)d_in[7];
    const float* wge = (const float*)d_in[8];
    const float* wue = (const float*)d_in[9];
    const float* wde = (const float*)d_in[10];
    float* out = (float*)d_out;

    float *pV,*pH,*pXN2;
    __half *pXNh,*pATTh,*pXN2h,*pHh,*pQhh,*pKhh,*pVt;
    __half *pWqh,*pWkh,*pWvh,*pWoh,*pWgeh,*pWueh,*pWdeh;
    cudaGetSymbolAddress((void**)&pV,    g_Vb);
    cudaGetSymbolAddress((void**)&pH,    g_Hb);
    cudaGetSymbolAddress((void**)&pXN2,  g_XN2);
    cudaGetSymbolAddress((void**)&pXNh,  g_XNh);
    cudaGetSymbolAddress((void**)&pATTh, g_ATTh);
    cudaGetSymbolAddress((void**)&pXN2h, g_XN2h);
    cudaGetSymbolAddress((void**)&pHh,   g_Hh);
    cudaGetSymbolAddress((void**)&pQhh,  g_Qh);
    cudaGetSymbolAddress((void**)&pKhh,  g_Kh);
    cudaGetSymbolAddress((void**)&pVt,   g_Vt);
    cudaGetSymbolAddress((void**)&pWqh,  g_Wqh);
    cudaGetSymbolAddress((void**)&pWkh,  g_Wkh);
    cudaGetSymbolAddress((void**)&pWvh,  g_Wvh);
    cudaGetSymbolAddress((void**)&pWoh,  g_Woh);
    cudaGetSymbolAddress((void**)&pWgeh, g_Wgeh);
    cudaGetSymbolAddress((void**)&pWueh, g_Wueh);
    cudaGetSymbolAddress((void**)&pWdeh, g_Wdeh);

    cudaFuncSetAttribute(k_gemm<16,EPI_ROPE,false,false>,
                         cudaFuncAttributeMaxDynamicSharedMemorySize, GEMM_SMEM);
    cudaFuncSetAttribute(k_gemm<16,EPI_RESID,false,false>,
                         cudaFuncAttributeMaxDynamicSharedMemorySize, GEMM_SMEM);
    cudaFuncSetAttribute(k_gemm_swiglu,
                         cudaFuncAttributeMaxDynamicSharedMemorySize, SWIGLU_SMEM);
    cudaFuncSetAttribute(k_gemm<32,EPI_DOWN,false,true,true>,
                         cudaFuncAttributeMaxDynamicSharedMemorySize, GEMM_SMEM);

    // side stream for expert-weight conversion, overlapped with attention path
    static cudaStream_t s2 = nullptr;
    static cudaEvent_t evFork = nullptr, evJoin = nullptr;
    if (!s2){
        cudaStreamCreateWithFlags(&s2, cudaStreamNonBlocking);
        cudaEventCreateWithFlags(&evFork, cudaEventDisableTiming);
        cudaEventCreateWithFlags(&evJoin, cudaEventDisableTiming);
    }

    k_reset<<<1, 32>>>();

    // ---- fork: expert weight conversions on s2 ----
    cudaEventRecord(evFork, 0);
    cudaStreamWaitEvent(s2, evFork, 0);
    {
        int ne4 = En*HIDn*(Dn/4), blk = 256, g2 = (ne4+blk-1)/blk;
        k_f2h2<<<dim3(g2,2), blk, 0, s2>>>((const float4*)wge, (const float4*)wue,
                                           (uint2*)pWgeh, (uint2*)pWueh, ne4);
        k_f2h<<<g2, blk, 0, s2>>>((const float4*)wde, (uint2*)pWdeh, ne4);
    }
    cudaEventRecord(evJoin, s2);

    // ---- main stream: attention path ----
    {
        int n4 = Dn*Dn/4, blk = 256, g1 = (n4+blk-1)/blk;
        k_f2h4<<<dim3(g1,4), blk>>>((const float4*)wq, (const float4*)wk,
                                    (const float4*)wv, (const float4*)wo,
                                    (uint2*)pWqh, (uint2*)pWkh,
                                    (uint2*)pWvh, (uint2*)pWoh, n4);
    }

    k_rmsnorm<<<Tn, 256>>>(x, anw, nullptr, pXNh);

    // QKV GEMM with fused RoPE: Q/K -> fp16 (rotated), V -> fp32
    k_gemm<16,EPI_ROPE,false,false><<<dim3(8,16,3), 256, GEMM_SMEM>>>(
        pXNh, Dn, pWqh, pWkh, pWvh, 0, Dn, pQhh, pKhh, pV, Dn, nullptr, nullptr);

    // V -> transposed fp16
    k_vtrans<<<dim3(Bn*NHn, Sn/64), 128>>>(pV, pVt);

    // HMMA flash attention
    k_attn_mma<<<dim3(Bn*NHn, Sn/64), 128>>>(pQhh, pKhh, pVt, pATTh);

    k_gemm<16,EPI_RESID,false,false><<<dim3(8,16,1), 256, GEMM_SMEM>>>(
        pATTh, Dn, pWoh, pWoh, pWoh, 0, Dn, pH, pH, pH, Dn, x, out);

    k_rmsnorm<<<Tn, 256>>>(pH, fnw, pXN2, pXN2h);

    k_gate<<<Tn, 256>>>(pXN2, gw);
    int write_aux = (out_size > Tn*Dn) ? 1 : 0;
    k_offsets<<<1, 256>>>(out, write_aux);
    k_scatter<<<(Tn+255)/256, 256>>>();

    // ---- join: expert GEMMs need the converted weights ----
    cudaStreamWaitEvent(0, evJoin, 0);

    // fused gate+up+SwiGLU GEMM -> Hh directly
    k_gemm_swiglu<<<dim3(32, MAXROWS/128), 256, SWIGLU_SMEM>>>(
        pXN2h, Dn, pWgeh, pWueh, (long)HIDn*Dn, Dn, pHh, HIDn);

    // down GEMM: split-K x2 (atomics accumulate across splits)
    k_gemm<32,EPI_DOWN,false,true,true><<<dim3(8, MAXROWS/128, 2), 256, GEMM_SMEM>>>(
        pHh, HIDn, pWdeh, pWdeh, pWdeh, (long)Dn*HIDn, HIDn, out, out, out, Dn,
        nullptr, nullptr);
}

// round 14
// speedup vs baseline: 1.0472x; 1.0472x over previous
#include <cuda_runtime.h>
#include <cuda_fp16.h>
#include <math.h>
#include <stdint.h>

// Problem constants
#define Bn 2
#define Sn 1024
#define Dn 1024
#define NHn 16
#define HDn 64
#define En 8
#define HIDn 4096
#define Tn (Bn*Sn)          // 2048 tokens
#define MAXROWS 5248        // >= 4096 assignments + 8*127 padding, mult of 128

// ---------------- scratch (static device globals; no allocation) -------------
static __device__ __half g_XNh [Tn*Dn];
static __device__ __half g_Vh  [Tn*Dn];
static __device__ __half g_Qh  [Tn*Dn];
static __device__ __half g_Kh  [Tn*Dn];
static __device__ __half g_Vt  [(size_t)Bn*NHn*HDn*Sn];
static __device__ __half g_ATTh[Tn*Dn];
static __device__ float  g_Hb  [Tn*Dn];
static __device__ float  g_XN2 [Tn*Dn];
static __device__ __half g_XN2h[Tn*Dn];
static __device__ __half g_GBh [(size_t)MAXROWS*HIDn];
static __device__ __half g_UBh [(size_t)MAXROWS*HIDn];
static __device__ __half g_Hh  [(size_t)MAXROWS*HIDn];
// fp16 weights
static __device__ __half g_Wqh[Dn*Dn];
static __device__ __half g_Wkh[Dn*Dn];
static __device__ __half g_Wvh[Dn*Dn];
static __device__ __half g_Woh[Dn*Dn];
static __device__ __half g_Wgeh[(size_t)En*HIDn*Dn];
static __device__ __half g_Wueh[(size_t)En*HIDn*Dn];
static __device__ __half g_Wdeh[(size_t)En*Dn*HIDn];
// routing
static __device__ int   g_cnt[En];
static __device__ int   g_cursor[En];
static __device__ int   g_rowtok[MAXROWS];
static __device__ int   g_rowexp[MAXROWS];
static __device__ float g_rowgate[MAXROWS];
static __device__ int   g_totalrows;
static __device__ float g_gsum[En];
static __device__ float g_psum[En];
static __device__ int   g_expid[Tn*2];
static __device__ float g_gateval[Tn*2];

// ======================= PTX helpers =========================================
static __device__ __forceinline__ uint32_t smem_u32_(const void* p){
    uint32_t a;
    asm("{ .reg .u64 t; cvta.to.shared.u64 t, %1; cvt.u32.u64 %0, t; }"
        : "=r"(a) : "l"(p));
    return a;
}

#define LDSM_X4(r0,r1,r2,r3,addr) \
    asm volatile("ldmatrix.sync.aligned.m8n8.x4.shared.b16 {%0,%1,%2,%3}, [%4];" \
        : "=r"(r0),"=r"(r1),"=r"(r2),"=r"(r3) : "r"(addr))

#define MMA16816(c,a,b) \
    asm volatile("mma.sync.aligned.m16n8k16.row.col.f32.f16.f16.f32 " \
        "{%0,%1,%2,%3}, {%4,%5,%6,%7}, {%8,%9}, {%0,%1,%2,%3};" \
        : "+f"((c)[0]),"+f"((c)[1]),"+f"((c)[2]),"+f"((c)[3]) \
        : "r"((a)[0]),"r"((a)[1]),"r"((a)[2]),"r"((a)[3]), \
          "r"((b)[0]),"r"((b)[1]))

#define CP_COMMIT() asm volatile("cp.async.commit_group;" ::: "memory")
#define CP_WAIT(N)  asm volatile("cp.async.wait_group %0;" :: "n"(N) : "memory")

static __device__ __forceinline__ void cp16_(uint32_t dst, const void* src, int srcsize){
    asm volatile("cp.async.cg.shared.global [%0], [%1], 16, %2;"
        :: "r"(dst), "l"((unsigned long long)__cvta_generic_to_global(src)),
           "r"(srcsize) : "memory");
}

// ============================== small kernels ================================
__global__ void k_reset() {
    int i = threadIdx.x;
    if (i < En) { g_cnt[i] = 0; g_gsum[i] = 0.f; g_psum[i] = 0.f; }
}

static __device__ __forceinline__ void f2h_one_(const float4* s, uint2* d, int i){
    float4 v = s[i];
    __half2 h0 = __floats2half2_rn(v.x, v.y);
    __half2 h1 = __floats2half2_rn(v.z, v.w);
    uint2 o;
    o.x = *reinterpret_cast<uint32_t*>(&h0);
    o.y = *reinterpret_cast<uint32_t*>(&h1);
    d[i] = o;
}

__global__ void k_f2h2(const float4* __restrict__ s0, const float4* __restrict__ s1,
                       uint2* __restrict__ d0, uint2* __restrict__ d1, int n4){
    int i = blockIdx.x*blockDim.x + threadIdx.x;
    if (i >= n4) return;
    if (blockIdx.y == 0) f2h_one_(s0, d0, i);
    else                 f2h_one_(s1, d1, i);
}

__global__ void k_f2h4(const float4* __restrict__ s0, const float4* __restrict__ s1,
                       const float4* __restrict__ s2p, const float4* __restrict__ s3,
                       uint2* __restrict__ d0, uint2* __restrict__ d1,
                       uint2* __restrict__ d2, uint2* __restrict__ d3, int n4){
    int i = blockIdx.x*blockDim.x + threadIdx.x;
    if (i >= n4) return;
    switch (blockIdx.y){
        case 0: f2h_one_(s0, d0, i); break;
        case 1: f2h_one_(s1, d1, i); break;
        case 2: f2h_one_(s2p, d2, i); break;
        default: f2h_one_(s3, d3, i); break;
    }
}

__global__ void k_f2h(const float4* __restrict__ s, uint2* __restrict__ d, int n4){
    int i = blockIdx.x*blockDim.x + threadIdx.x;
    if (i >= n4) return;
    f2h_one_(s, d, i);
}

__global__ void k_rmsnorm(const float* __restrict__ x, const float* __restrict__ w,
                          float* __restrict__ y, __half* __restrict__ yh) {
    int t = blockIdx.x;
    const float* xr = x + (size_t)t * Dn;
    int base = threadIdx.x * 4;
    float4 xv = *(const float4*)(xr + base);
    float ss = xv.x*xv.x + xv.y*xv.y + xv.z*xv.z + xv.w*xv.w;
    #pragma unroll
    for (int o = 16; o; o >>= 1) ss += __shfl_xor_sync(0xffffffffu, ss, o);
    __shared__ float ws[8];
    if ((threadIdx.x & 31) == 0) ws[threadIdx.x >> 5] = ss;
    __syncthreads();
    float tot = ws[0]+ws[1]+ws[2]+ws[3]+ws[4]+ws[5]+ws[6]+ws[7];
    float sc = rsqrtf(tot * (1.f/(float)Dn) + 1e-6f);
    float4 wv = *(const float4*)(w + base);
    float4 o4;
    o4.x = wv.x*xv.x*sc; o4.y = wv.y*xv.y*sc;
    o4.z = wv.z*xv.z*sc; o4.w = wv.w*xv.w*sc;
    if (y) *(float4*)(y + (size_t)t*Dn + base) = o4;
    __half2 h0 = __floats2half2_rn(o4.x, o4.y);
    __half2 h1 = __floats2half2_rn(o4.z, o4.w);
    uint2 ho;
    ho.x = *reinterpret_cast<uint32_t*>(&h0);
    ho.y = *reinterpret_cast<uint32_t*>(&h1);
    *(uint2*)(yh + (size_t)t*Dn + base) = ho;
}

// ===================== mma.sync GEMM (HMMA tensor path) ======================
#define EPI_PLAIN 0
#define EPI_RESID 1
#define EPI_DOWN  2
#define EPI_HALF  3
#define EPI_ROPE  4
#define GEMM_SMEM (3*32768)

template<int NITER, int EPI, bool GATHER, bool ESEL, bool ZSPLIT=false>
__global__ __launch_bounds__(256)
void k_gemm(const __half* __restrict__ A0, int lda,
            const __half* __restrict__ B0, const __half* __restrict__ B1,
            const __half* __restrict__ B2,
            long bstride, int ldb,
            void* __restrict__ C0v, void* __restrict__ C1v, void* __restrict__ C2v,
            int ldc,
            const float* __restrict__ resid, float* __restrict__ Cdual)
{
    constexpr int S = 3;
    int mt = blockIdx.y, nt = blockIdx.x;
    if (ESEL && mt*128 >= g_totalrows) return;
    const __half* Bh = ZSPLIT ? B0
        : ((blockIdx.z==0) ? B0 : ((blockIdx.z==1) ? B1 : B2));
    void* Cv = ZSPLIT ? C0v
        : ((blockIdx.z==0) ? C0v : ((blockIdx.z==1) ? C1v : C2v));
    if (ESEL) Bh += (long)g_rowexp[mt*128] * bstride;
    long koff = ZSPLIT ? (long)blockIdx.z * (NITER*64) : 0;

    extern __shared__ __align__(128) char sm_[];
    uint32_t sbase = smem_u32_(sm_);

    int tid = threadIdx.x, lane = tid & 31, wid = tid >> 5;
    int warp_m = wid & 3, warp_n = wid >> 2;

    int lrow = tid >> 1;
    int lc0  = (tid & 1) * 4;
    const __half* asrc;
    bool avalid = true;
    if (GATHER){
        int tok = g_rowtok[mt*128 + lrow];
        avalid = (tok >= 0);
        asrc = A0 + (avalid ? (size_t)tok * lda : 0);
    } else {
        asrc = A0 + (size_t)(mt*128 + lrow) * lda;
    }
    asrc += koff;
    const __half* bsrc = Bh + (size_t)(nt*128 + lrow) * ldb + koff;
    int asz = avalid ? 16 : 0;
    uint32_t arow_s = sbase + lrow*128;
    uint32_t brow_s = arow_s + 16384;

    auto stg = [&](int it){
        int stage = it % S;
        uint32_t so = (uint32_t)stage * 32768u;
        const char* ag = (const char*)(asrc + it*64);
        const char* bg = (const char*)(bsrc + it*64);
        #pragma unroll
        for (int i = 0; i < 4; i++){
            int c = lc0 + i;
            uint32_t sw = (uint32_t)((c ^ (lrow & 7)) * 16);
            cp16_(arow_s + so + sw, ag + c*16, asz);
            cp16_(brow_s + so + sw, bg + c*16, 16);
        }
    };

    float acc[2][8][4];
    #pragma unroll
    for (int i=0;i<2;i++)
        #pragma unroll
        for (int j=0;j<8;j++)
            #pragma unroll
            for (int k=0;k<4;k++) acc[i][j][k]=0.f;

    #pragma unroll
    for (int it = 0; it < S-1; it++){ stg(it); CP_COMMIT(); }

    int a_rlo = (lane & 15);
    int a_chk = (lane >> 4);
    int b_rlo = (lane & 7) + ((lane & 16) ? 8 : 0);
    int b_chk = (lane >> 3) & 1;

    for (int it = 0; it < NITER; it++){
        CP_WAIT(S-2);
        __syncthreads();
        if (it + S-1 < NITER) stg(it + S-1);
        CP_COMMIT();

        uint32_t so = (uint32_t)(it % S) * 32768u;
        uint32_t abase = sbase + so;
        uint32_t bbase = abase + 16384;

        #pragma unroll
        for (int ks = 0; ks < 4; ks++){
            uint32_t a[2][4];
            #pragma unroll
            for (int mtile = 0; mtile < 2; mtile++){
                int row = warp_m*32 + mtile*16 + a_rlo;
                int chunk = 2*ks + a_chk;
                uint32_t addr = abase + row*128 + ((chunk ^ (row & 7)) * 16);
                LDSM_X4(a[mtile][0], a[mtile][1], a[mtile][2], a[mtile][3], addr);
            }
            uint32_t b[8][2];
            #pragma unroll
            for (int n2 = 0; n2 < 4; n2++){
                int row = warp_n*64 + n2*16 + b_rlo;
                int chunk = 2*ks + b_chk;
                uint32_t addr = bbase + row*128 + ((chunk ^ (row & 7)) * 16);
                uint32_t r0,r1,r2,r3;
                LDSM_X4(r0, r1, r2, r3, addr);
                b[2*n2][0]=r0; b[2*n2][1]=r1;
                b[2*n2+1][0]=r2; b[2*n2+1][1]=r3;
            }
            #pragma unroll
            for (int mtile = 0; mtile < 2; mtile++)
                #pragma unroll
                for (int n8 = 0; n8 < 8; n8++)
                    MMA16816(acc[mtile][n8], a[mtile], b[n8]);
        }
        __syncthreads();
    }

    // ---- epilogue ----
    int m0 = mt*128 + warp_m*32;
    int n0 = nt*128 + warp_n*64;
    int gq = lane >> 2, tq = lane & 3;
    #pragma unroll
    for (int mtile = 0; mtile < 2; mtile++){
        int r_lo = m0 + mtile*16 + gq;
        int r_hi = r_lo + 8;
        if (EPI == EPI_DOWN){
            float* C = (float*)Cv;
            int tok_lo = g_rowtok[r_lo], tok_hi = g_rowtok[r_hi];
            float gl = g_rowgate[r_lo], gh = g_rowgate[r_hi];
            #pragma unroll
            for (int n8 = 0; n8 < 8; n8++){
                int col = n0 + n8*8 + tq*2;
                if (tok_lo >= 0){
                    size_t o = (size_t)tok_lo*ldc + col;
                    atomicAdd(&C[o],   gl*acc[mtile][n8][0]);
                    atomicAdd(&C[o+1], gl*acc[mtile][n8][1]);
                }
                if (tok_hi >= 0){
                    size_t o = (size_t)tok_hi*ldc + col;
                    atomicAdd(&C[o],   gh*acc[mtile][n8][2]);
                    atomicAdd(&C[o+1], gh*acc[mtile][n8][3]);
                }
            }
        } else if (EPI == EPI_RESID){
            float* C = (float*)Cv;
            #pragma unroll
            for (int n8 = 0; n8 < 8; n8++){
                int col = n0 + n8*8 + tq*2;
                size_t o_lo = (size_t)r_lo*ldc + col;
                size_t o_hi = (size_t)r_hi*ldc + col;
                float2 rv0 = *(const float2*)(resid + o_lo);
                float2 rv1 = *(const float2*)(resid + o_hi);
                float2 v0, v1;
                v0.x = acc[mtile][n8][0] + rv0.x;
                v0.y = acc[mtile][n8][1] + rv0.y;
                v1.x = acc[mtile][n8][2] + rv1.x;
                v1.y = acc[mtile][n8][3] + rv1.y;
                *(float2*)(C + o_lo) = v0;
                *(float2*)(C + o_hi) = v1;
                *(float2*)(Cdual + o_lo) = v0;
                *(float2*)(Cdual + o_hi) = v1;
            }
        } else if (EPI == EPI_HALF){
            __half* Ch = (__half*)Cv;
            #pragma unroll
            for (int n8 = 0; n8 < 8; n8++){
                int col = n0 + n8*8 + tq*2;
                __half2 v0 = __floats2half2_rn(acc[mtile][n8][0], acc[mtile][n8][1]);
                __half2 v1 = __floats2half2_rn(acc[mtile][n8][2], acc[mtile][n8][3]);
                *(__half2*)(Ch + (size_t)r_lo*ldc + col) = v0;
                *(__half2*)(Ch + (size_t)r_hi*ldc + col) = v1;
            }
        } else if (EPI == EPI_ROPE){
            if (blockIdx.z == 2){
                // V: fp16 store
                __half* Ch = (__half*)Cv;
                #pragma unroll
                for (int n8 = 0; n8 < 8; n8++){
                    int col = n0 + n8*8 + tq*2;
                    __half2 v0 = __floats2half2_rn(acc[mtile][n8][0], acc[mtile][n8][1]);
                    __half2 v1 = __floats2half2_rn(acc[mtile][n8][2], acc[mtile][n8][3]);
                    *(__half2*)(Ch + (size_t)r_lo*ldc + col) = v0;
                    *(__half2*)(Ch + (size_t)r_hi*ldc + col) = v1;
                }
            } else {
                __half* Ch = (__half*)Cv;
                int s_lo = r_lo & (Sn-1);
                int s_hi = r_hi & (Sn-1);
                #pragma unroll
                for (int n8 = 0; n8 < 4; n8++){
                    int col = n0 + n8*8 + tq*2;
                    int i0 = col & 63;                      // < 32
                    float inv0 = powf(10000.f, (float)(-2*i0)   * (1.f/64.f));
                    float inv1 = powf(10000.f, (float)(-2*(i0+1)) * (1.f/64.f));
                    float c0l,s0l,c1l,s1l,c0h,s0h,c1h,s1h;
                    sincosf((float)s_lo*inv0, &s0l, &c0l);
                    sincosf((float)s_lo*inv1, &s1l, &c1l);
                    sincosf((float)s_hi*inv0, &s0h, &c0h);
                    sincosf((float)s_hi*inv1, &s1h, &c1h);
                    float a0 = acc[mtile][n8][0],   a1 = acc[mtile][n8][1];
                    float b0 = acc[mtile][n8+4][0], b1 = acc[mtile][n8+4][1];
                    float a2 = acc[mtile][n8][2],   a3 = acc[mtile][n8][3];
                    float b2 = acc[mtile][n8+4][2], b3 = acc[mtile][n8+4][3];
                    __half2 lo_a = __floats2half2_rn(a0*c0l - b0*s0l, a1*c1l - b1*s1l);
                    __half2 lo_b = __floats2half2_rn(b0*c0l + a0*s0l, b1*c1l + a1*s1l);
                    __half2 hi_a = __floats2half2_rn(a2*c0h - b2*s0h, a3*c1h - b3*s1h);
                    __half2 hi_b = __floats2half2_rn(b2*c0h + a2*s0h, b3*c1h + a3*s1h);
                    *(__half2*)(Ch + (size_t)r_lo*ldc + col)      = lo_a;
                    *(__half2*)(Ch + (size_t)r_lo*ldc + col + 32) = lo_b;
                    *(__half2*)(Ch + (size_t)r_hi*ldc + col)      = hi_a;
                    *(__half2*)(Ch + (size_t)r_hi*ldc + col + 32) = hi_b;
                }
            }
        } else {
            float* C = (float*)Cv;
            #pragma unroll
            for (int n8 = 0; n8 < 8; n8++){
                int col = n0 + n8*8 + tq*2;
                float2 v0, v1;
                v0.x = acc[mtile][n8][0]; v0.y = acc[mtile][n8][1];
                v1.x = acc[mtile][n8][2]; v1.y = acc[mtile][n8][3];
                *(float2*)(C + (size_t)r_lo*ldc + col) = v0;
                *(float2*)(C + (size_t)r_hi*ldc + col) = v1;
            }
        }
    }
}

// ===== V transpose: fp16 [t][h*64+d] -> fp16 Vt[bh][d][s], padded smem ======
// Row padded to 72 halves (144 B) so 16B vector stores stay aligned.
__global__ void k_vtrans(const __half* __restrict__ V, __half* __restrict__ Vt)
{
    __shared__ __align__(16) __half ts[64][72];
    int bh = blockIdx.x, st = blockIdx.y;
    int b = bh >> 4, h = bh & 15;
    int tid = threadIdx.x;                 // 128 threads
    int row = tid >> 1, c0 = (tid & 1) * 32;
    const uint4* src = (const uint4*)(V + ((size_t)(b*Sn + st*64 + row))*Dn
                                        + h*HDn + c0);
    #pragma unroll
    for (int i = 0; i < 4; i++){
        uint4 v = src[i];
        *(uint4*)&ts[row][c0 + 8*i] = v;
    }
    __syncthreads();
    __half* dst = Vt + ((size_t)bh*HDn + row)*Sn + st*64 + c0;
    #pragma unroll
    for (int i = 0; i < 32; i += 2){
        __half2 hv = __halves2half2(ts[c0+i][row], ts[c0+i+1][row]);
        *(__half2*)(dst + i) = hv;
    }
}

// ================= HMMA flash attention (m16n8k16) ===========================
__global__ __launch_bounds__(128)
void k_attn_mma(const __half* __restrict__ Qh, const __half* __restrict__ Kh,
                const __half* __restrict__ Vt, __half* __restrict__ O)
{
    __shared__ __align__(128) char sm[3*8192];
    uint32_t qs = smem_u32_(sm);
    uint32_t ks = qs + 8192;
    uint32_t vs = qs + 16384;

    int bh = blockIdx.x;
    int qt = blockIdx.y;
    int b = bh >> 4, h = bh & 15;
    int tid = threadIdx.x, lane = tid & 31, wid = tid >> 5;
    int q0 = qt*64;

    int srow = tid >> 1, sc0 = (tid & 1) * 4;
    int gq = lane >> 2, tq = lane & 3;
    int a_rlo = lane & 15, a_chk = lane >> 4;
    int b_rlo = (lane & 7) + ((lane & 16) ? 8 : 0);
    int b_chk = (lane >> 3) & 1;

    {
        const uint4* src = (const uint4*)(Qh + ((size_t)(b*Sn + q0 + srow))*Dn + h*HDn);
        #pragma unroll
        for (int i = 0; i < 4; i++){
            int c = sc0 + i;
            *(uint4*)(sm + srow*128 + ((c ^ (srow & 7)) * 16)) = src[c];
        }
    }
    __syncthreads();

    uint32_t qa[4][4];
    #pragma unroll
    for (int kc = 0; kc < 4; kc++){
        int row = wid*16 + a_rlo;
        int chunk = kc*2 + a_chk;
        uint32_t addr = qs + row*128 + ((chunk ^ (row & 7)) * 16);
        LDSM_X4(qa[kc][0], qa[kc][1], qa[kc][2], qa[kc][3], addr);
    }

    float o_[8][4];
    #pragma unroll
    for (int j=0;j<8;j++)
        #pragma unroll
        for (int k=0;k<4;k++) o_[j][k]=0.f;
    float m_lo = -1e30f, m_hi = -1e30f, l_lo = 0.f, l_hi = 0.f;

    for (int kt = 0; kt <= qt; kt++){
        {
            const uint4* ksrc = (const uint4*)(Kh + ((size_t)(b*Sn + kt*64 + srow))*Dn + h*HDn);
            const uint4* vsrc = (const uint4*)(Vt + ((size_t)bh*HDn + srow)*Sn + kt*64);
            #pragma unroll
            for (int i = 0; i < 4; i++){
                int c = sc0 + i;
                uint32_t sw = (uint32_t)((c ^ (srow & 7)) * 16);
                *(uint4*)(sm + 8192  + srow*128 + sw) = ksrc[c];
                *(uint4*)(sm + 16384 + srow*128 + sw) = vsrc[c];
            }
        }
        __syncthreads();

        float s_[8][4];
        #pragma unroll
        for (int j=0;j<8;j++)
            #pragma unroll
            for (int k=0;k<4;k++) s_[j][k]=0.f;
        #pragma unroll
        for (int kc = 0; kc < 4; kc++){
            uint32_t kb[8][2];
            #pragma unroll
            for (int n2 = 0; n2 < 4; n2++){
                int row = n2*16 + b_rlo;
                int chunk = kc*2 + b_chk;
                uint32_t addr = ks + row*128 + ((chunk ^ (row & 7)) * 16);
                uint32_t r0,r1,r2,r3;
                LDSM_X4(r0, r1, r2, r3, addr);
                kb[2*n2][0]=r0; kb[2*n2][1]=r1;
                kb[2*n2+1][0]=r2; kb[2*n2+1][1]=r3;
            }
            #pragma unroll
            for (int j = 0; j < 8; j++)
                MMA16816(s_[j], qa[kc], kb[j]);
        }

        int row_lo = q0 + wid*16 + gq;
        int row_hi = row_lo + 8;
        #pragma unroll
        for (int j = 0; j < 8; j++){
            int c0 = kt*64 + j*8 + tq*2;
            int c1 = c0 + 1;
            s_[j][0] = (c0 <= row_lo) ? s_[j][0]*0.125f : -1e30f;
            s_[j][1] = (c1 <= row_lo) ? s_[j][1]*0.125f : -1e30f;
            s_[j][2] = (c0 <= row_hi) ? s_[j][2]*0.125f : -1e30f;
            s_[j][3] = (c1 <= row_hi) ? s_[j][3]*0.125f : -1e30f;
        }

        float tm_lo = -1e30f, tm_hi = -1e30f;
        #pragma unroll
        for (int j = 0; j < 8; j++){
            tm_lo = fmaxf(tm_lo, fmaxf(s_[j][0], s_[j][1]));
            tm_hi = fmaxf(tm_hi, fmaxf(s_[j][2], s_[j][3]));
        }
        tm_lo = fmaxf(tm_lo, __shfl_xor_sync(0xffffffffu, tm_lo, 1));
        tm_lo = fmaxf(tm_lo, __shfl_xor_sync(0xffffffffu, tm_lo, 2));
        tm_hi = fmaxf(tm_hi, __shfl_xor_sync(0xffffffffu, tm_hi, 1));
        tm_hi = fmaxf(tm_hi, __shfl_xor_sync(0xffffffffu, tm_hi, 2));
        float mn_lo = fmaxf(m_lo, tm_lo);
        float mn_hi = fmaxf(m_hi, tm_hi);
        float corr_lo = __expf(m_lo - mn_lo);
        float corr_hi = __expf(m_hi - mn_hi);
        float rs_lo = 0.f, rs_hi = 0.f;
        #pragma unroll
        for (int j = 0; j < 8; j++){
            s_[j][0] = __expf(s_[j][0] - mn_lo);
            s_[j][1] = __expf(s_[j][1] - mn_lo);
            s_[j][2] = __expf(s_[j][2] - mn_hi);
            s_[j][3] = __expf(s_[j][3] - mn_hi);
            rs_lo += s_[j][0] + s_[j][1];
            rs_hi += s_[j][2] + s_[j][3];
        }
        rs_lo += __shfl_xor_sync(0xffffffffu, rs_lo, 1);
        rs_lo += __shfl_xor_sync(0xffffffffu, rs_lo, 2);
        rs_hi += __shfl_xor_sync(0xffffffffu, rs_hi, 1);
        rs_hi += __shfl_xor_sync(0xffffffffu, rs_hi, 2);
        l_lo = l_lo*corr_lo + rs_lo;
        l_hi = l_hi*corr_hi + rs_hi;
        m_lo = mn_lo; m_hi = mn_hi;
        #pragma unroll
        for (int j = 0; j < 8; j++){
            o_[j][0] *= corr_lo; o_[j][1] *= corr_lo;
            o_[j][2] *= corr_hi; o_[j][3] *= corr_hi;
        }

        uint32_t pa[4][4];
        #pragma unroll
        for (int kc = 0; kc < 4; kc++){
            __half2 h0 = __floats2half2_rn(s_[2*kc][0],   s_[2*kc][1]);
            __half2 h1 = __floats2half2_rn(s_[2*kc][2],   s_[2*kc][3]);
            __half2 h2 = __floats2half2_rn(s_[2*kc+1][0], s_[2*kc+1][1]);
            __half2 h3 = __floats2half2_rn(s_[2*kc+1][2], s_[2*kc+1][3]);
            pa[kc][0] = *reinterpret_cast<uint32_t*>(&h0);
            pa[kc][1] = *reinterpret_cast<uint32_t*>(&h1);
            pa[kc][2] = *reinterpret_cast<uint32_t*>(&h2);
            pa[kc][3] = *reinterpret_cast<uint32_t*>(&h3);
        }

        #pragma unroll
        for (int kc = 0; kc < 4; kc++){
            uint32_t vb[8][2];
            #pragma unroll
            for (int n2 = 0; n2 < 4; n2++){
                int row = n2*16 + b_rlo;
                int chunk = kc*2 + b_chk;
                uint32_t addr = vs + row*128 + ((chunk ^ (row & 7)) * 16);
                uint32_t r0,r1,r2,r3;
                LDSM_X4(r0, r1, r2, r3, addr);
                vb[2*n2][0]=r0; vb[2*n2][1]=r1;
                vb[2*n2+1][0]=r2; vb[2*n2+1][1]=r3;
            }
            #pragma unroll
            for (int j = 0; j < 8; j++)
                MMA16816(o_[j], pa[kc], vb[j]);
        }
        __syncthreads();
    }

    float inv_lo = 1.f/l_lo, inv_hi = 1.f/l_hi;
    int row_lo = q0 + wid*16 + gq;
    int row_hi = row_lo + 8;
    #pragma unroll
    for (int j = 0; j < 8; j++){
        int col = j*8 + tq*2;
        __half2 v0 = __floats2half2_rn(o_[j][0]*inv_lo, o_[j][1]*inv_lo);
        __half2 v1 = __floats2half2_rn(o_[j][2]*inv_hi, o_[j][3]*inv_hi);
        *(__half2*)(O + ((size_t)(b*Sn + row_lo))*Dn + h*HDn + col) = v0;
        *(__half2*)(O + ((size_t)(b*Sn + row_hi))*Dn + h*HDn + col) = v1;
    }
}

// =============================== gating / MoE ================================
__global__ void k_gate(const float* __restrict__ xn, const float* __restrict__ gw)
{
    int t = blockIdx.x;
    int w = threadIdx.x >> 5, lane = threadIdx.x & 31;
    const float* xr = xn + (size_t)t * Dn;
    const float* gr = gw + (size_t)w * Dn;
    float acc = 0.f;
    for (int d = lane; d < Dn; d += 32) acc = fmaf(xr[d], gr[d], acc);
    #pragma unroll
    for (int o=16;o;o>>=1) acc += __shfl_xor_sync(0xffffffffu, acc, o);
    __shared__ float lg[En];
    if (lane == 0) lg[w] = acc;
    __syncthreads();
    if (threadIdx.x == 0){
        int i1 = 0;
        for (int e=1;e<En;e++) if (lg[e] > lg[i1]) i1 = e;
        int i2 = -1;
        for (int e=0;e<En;e++){
            if (e == i1) continue;
            if (i2 < 0 || lg[e] > lg[i2]) i2 = e;
        }
        float l1 = lg[i1], l2 = lg[i2];
        float e2 = expf(l2 - l1);
        float inv = 1.f/(1.f + e2);
        float gv1 = inv, gv2 = e2*inv;
        g_expid[t*2]   = i1; g_expid[t*2+1]   = i2;
        g_gateval[t*2] = gv1; g_gateval[t*2+1] = gv2;
        atomicAdd(&g_cnt[i1], 1); atomicAdd(&g_cnt[i2], 1);
        atomicAdd(&g_gsum[i1], gv1); atomicAdd(&g_gsum[i2], gv2);
        float mx = lg[0];
        for (int e=1;e<En;e++) mx = fmaxf(mx, lg[e]);
        float pe[En]; float se = 0.f;
        for (int e=0;e<En;e++){ pe[e] = expf(lg[e]-mx); se += pe[e]; }
        float pinv = 1.f/se;
        for (int e=0;e<En;e++) atomicAdd(&g_psum[e], pe[e]*pinv);
    }
}

// merged offsets + row-init + scatter (single block)
__global__ void k_route(float* __restrict__ out, int write_aux)
{
    __shared__ int soff[En+1];
    if (threadIdx.x == 0){
        int tot = 0;
        for (int e=0;e<En;e++){
            soff[e] = tot;
            g_cursor[e] = tot;
            tot += ((g_cnt[e] + 127) >> 7) << 7;
        }
        soff[En] = tot;
        g_totalrows = tot;
        if (write_aux){
            float sacc = 0.f;
            for (int e=0;e<En;e++) sacc += g_gsum[e]*g_psum[e];
            out[(size_t)Tn*Dn] = (float)En * sacc / ((float)Tn*(float)Tn);
        }
    }
    __syncthreads();
    int tot = soff[En];
    for (int r = threadIdx.x; r < tot; r += blockDim.x){
        int e = 0;
        while (e+1 < En && r >= soff[e+1]) e++;
        g_rowexp[r] = e;
        g_rowtok[r] = -1;
    }
    __syncthreads();
    for (int t = threadIdx.x; t < Tn; t += blockDim.x){
        #pragma unroll
        for (int k=0;k<2;k++){
            int e = g_expid[t*2+k];
            int pos = atomicAdd(&g_cursor[e], 1);
            g_rowtok[pos] = t;
            g_rowgate[pos] = g_gateval[t*2+k];
        }
    }
}

// H = silu(G) * U, fp16 in -> fp16 out
__global__ void k_silumul()
{
    size_t i4 = ((size_t)blockIdx.x*blockDim.x + threadIdx.x) * 4;
    size_t n = (size_t)g_totalrows * HIDn;
    if (i4 >= n) return;
    uint2 gp = *(uint2*)&g_GBh[i4];
    uint2 up = *(uint2*)&g_UBh[i4];
    __half2 g0 = *reinterpret_cast<__half2*>(&gp.x);
    __half2 g1 = *reinterpret_cast<__half2*>(&gp.y);
    __half2 u0 = *reinterpret_cast<__half2*>(&up.x);
    __half2 u1 = *reinterpret_cast<__half2*>(&up.y);
    float gx = __low2float(g0),  gy = __high2float(g0);
    float gz = __low2float(g1),  gw_ = __high2float(g1);
    float ux = __low2float(u0),  uy = __high2float(u0);
    float uz = __low2float(u1),  uw = __high2float(u1);
    float a = (gx / (1.f + __expf(-gx))) * ux;
    float b = (gy / (1.f + __expf(-gy))) * uy;
    float c = (gz / (1.f + __expf(-gz))) * uz;
    float d = (gw_ / (1.f + __expf(-gw_))) * uw;
    __half2 h0 = __floats2half2_rn(a, b);
    __half2 h1 = __floats2half2_rn(c, d);
    uint2 o;
    o.x = *reinterpret_cast<uint32_t*>(&h0);
    o.y = *reinterpret_cast<uint32_t*>(&h1);
    *(uint2*)&g_Hh[i4] = o;
}

// ---------------------------------------------------------------------------
extern "C" void kernel_launch(void* const* d_in, const int* in_sizes, int n_in,
                              void* d_out, int out_size)
{
    (void)in_sizes; (void)n_in;
    const float* x   = (const float*)d_in[0];
    const float* wq  = (const float*)d_in[1];
    const float* wk  = (const float*)d_in[2];
    const float* wv  = (const float*)d_in[3];
    const float* wo  = (const float*)d_in[4];
    const float* anw = (const float*)d_in[5];
    const float* fnw = (const float*)d_in[6];
    const float* gw  = (const float*)d_in[7];
    const float* wge = (const float*)d_in[8];
    const float* wue = (const float*)d_in[9];
    const float* wde = (const float*)d_in[10];
    float* out = (float*)d_out;

    float *pH,*pXN2;
    __half *pXNh,*pATTh,*pXN2h,*pHh,*pGh,*pUh,*pQhh,*pKhh,*pVt,*pVh;
    __half *pWqh,*pWkh,*pWvh,*pWoh,*pWgeh,*pWueh,*pWdeh;
    cudaGetSymbolAddress((void**)&pH,    g_Hb);
    cudaGetSymbolAddress((void**)&pXN2,  g_XN2);
    cudaGetSymbolAddress((void**)&pGh,   g_GBh);
    cudaGetSymbolAddress((void**)&pUh,   g_UBh);
    cudaGetSymbolAddress((void**)&pXNh,  g_XNh);
    cudaGetSymbolAddress((void**)&pATTh, g_ATTh);
    cudaGetSymbolAddress((void**)&pXN2h, g_XN2h);
    cudaGetSymbolAddress((void**)&pHh,   g_Hh);
    cudaGetSymbolAddress((void**)&pQhh,  g_Qh);
    cudaGetSymbolAddress((void**)&pKhh,  g_Kh);
    cudaGetSymbolAddress((void**)&pVt,   g_Vt);
    cudaGetSymbolAddress((void**)&pVh,   g_Vh);
    cudaGetSymbolAddress((void**)&pWqh,  g_Wqh);
    cudaGetSymbolAddress((void**)&pWkh,  g_Wkh);
    cudaGetSymbolAddress((void**)&pWvh,  g_Wvh);
    cudaGetSymbolAddress((void**)&pWoh,  g_Woh);
    cudaGetSymbolAddress((void**)&pWgeh, g_Wgeh);
    cudaGetSymbolAddress((void**)&pWueh, g_Wueh);
    cudaGetSymbolAddress((void**)&pWdeh, g_Wdeh);

    cudaFuncSetAttribute(k_gemm<16,EPI_ROPE,false,false>,
                         cudaFuncAttributeMaxDynamicSharedMemorySize, GEMM_SMEM);
    cudaFuncSetAttribute(k_gemm<16,EPI_RESID,false,false>,
                         cudaFuncAttributeMaxDynamicSharedMemorySize, GEMM_SMEM);
    cudaFuncSetAttribute(k_gemm<16,EPI_HALF,true,true>,
                         cudaFuncAttributeMaxDynamicSharedMemorySize, GEMM_SMEM);
    cudaFuncSetAttribute(k_gemm<32,EPI_DOWN,false,true,true>,
                         cudaFuncAttributeMaxDynamicSharedMemorySize, GEMM_SMEM);

    // side stream for ALL weight conversions, overlapped with main path
    static cudaStream_t s2 = nullptr;
    static cudaEvent_t evFork = nullptr, evJoin = nullptr, evJoinQKV = nullptr;
    if (!s2){
        cudaStreamCreateWithFlags(&s2, cudaStreamNonBlocking);
        cudaEventCreateWithFlags(&evFork, cudaEventDisableTiming);
        cudaEventCreateWithFlags(&evJoin, cudaEventDisableTiming);
        cudaEventCreateWithFlags(&evJoinQKV, cudaEventDisableTiming);
    }

    k_reset<<<1, 32>>>();

    // ---- fork: weight conversions on s2 (QKV/O first, then experts) ----
    cudaEventRecord(evFork, 0);
    cudaStreamWaitEvent(s2, evFork, 0);
    {
        int n4 = Dn*Dn/4, blk = 256, g1 = (n4+blk-1)/blk;
        k_f2h4<<<dim3(g1,4), blk, 0, s2>>>((const float4*)wq, (const float4*)wk,
                                           (const float4*)wv, (const float4*)wo,
                                           (uint2*)pWqh, (uint2*)pWkh,
                                           (uint2*)pWvh, (uint2*)pWoh, n4);
        cudaEventRecord(evJoinQKV, s2);
        int ne4 = En*HIDn*(Dn/4), g2 = (ne4+blk-1)/blk;
        k_f2h2<<<dim3(g2,2), blk, 0, s2>>>((const float4*)wge, (const float4*)wue,
                                           (uint2*)pWgeh, (uint2*)pWueh, ne4);
        k_f2h<<<g2, blk, 0, s2>>>((const float4*)wde, (uint2*)pWdeh, ne4);
    }
    cudaEventRecord(evJoin, s2);

    // ---- main stream: attention path (rmsnorm overlaps the conversions) ----
    k_rmsnorm<<<Tn, 256>>>(x, anw, nullptr, pXNh);

    cudaStreamWaitEvent(0, evJoinQKV, 0);

    // QKV GEMM with fused RoPE: Q/K -> fp16 (rotated), V -> fp16
    k_gemm<16,EPI_ROPE,false,false><<<dim3(8,16,3), 256, GEMM_SMEM>>>(
        pXNh, Dn, pWqh, pWkh, pWvh, 0, Dn, pQhh, pKhh, pVh, Dn, nullptr, nullptr);

    // V -> transposed fp16
    k_vtrans<<<dim3(Bn*NHn, Sn/64), 128>>>(pVh, pVt);

    // HMMA flash attention
    k_attn_mma<<<dim3(Bn*NHn, Sn/64), 128>>>(pQhh, pKhh, pVt, pATTh);

    k_gemm<16,EPI_RESID,false,false><<<dim3(8,16,1), 256, GEMM_SMEM>>>(
        pATTh, Dn, pWoh, pWoh, pWoh, 0, Dn, pH, pH, pH, Dn, x, out);

    k_rmsnorm<<<Tn, 256>>>(pH, fnw, pXN2, pXN2h);

    k_gate<<<Tn, 256>>>(pXN2, gw);
    int write_aux = (out_size > Tn*Dn) ? 1 : 0;
    k_route<<<1, 256>>>(out, write_aux);

    // ---- join: expert GEMMs need the converted weights ----
    cudaStreamWaitEvent(0, evJoin, 0);

    k_gemm<16,EPI_HALF,true,true><<<dim3(32, MAXROWS/128, 2), 256, GEMM_SMEM>>>(
        pXN2h, Dn, pWgeh, pWueh, pWueh, (long)HIDn*Dn, Dn, pGh, pUh, pUh, HIDn,
        nullptr, nullptr);

    k_silumul<<<(MAXROWS*(HIDn/4))/256, 256>>>();

    // down GEMM: split-K x2 (atomics accumulate across splits)
    k_gemm<32,EPI_DOWN,false,true,true><<<dim3(8, MAXROWS/128, 2), 256, GEMM_SMEM>>>(
        pHh, HIDn, pWdeh, pWdeh, pWdeh, (long)Dn*HIDn, HIDn, out, out, out, Dn,
        nullptr, nullptr);
}

// round 15
// speedup vs baseline: 1.0610x; 1.0131x over previous
#include <cuda_runtime.h>
#include <cuda_fp16.h>
#include <math.h>
#include <stdint.h>

// Problem constants
#define Bn 2
#define Sn 1024
#define Dn 1024
#define NHn 16
#define HDn 64
#define En 8
#define HIDn 4096
#define Tn (Bn*Sn)          // 2048 tokens
#define MAXROWS 5248        // >= 4096 assignments + 8*127 padding, mult of 128

// ---------------- scratch (static device globals; no allocation) -------------
static __device__ __half g_XNh [Tn*Dn];
static __device__ __half g_Vh  [Tn*Dn];
static __device__ __half g_Qh  [Tn*Dn];
static __device__ __half g_Kh  [Tn*Dn];
static __device__ __half g_Vt  [(size_t)Bn*NHn*HDn*Sn];
static __device__ __half g_ATTh[Tn*Dn];
static __device__ float  g_Hb  [Tn*Dn];
static __device__ float  g_XN2 [Tn*Dn];
static __device__ __half g_XN2h[Tn*Dn];
static __device__ __half g_GBh [(size_t)MAXROWS*HIDn];
static __device__ __half g_UBh [(size_t)MAXROWS*HIDn];
static __device__ __half g_Hh  [(size_t)MAXROWS*HIDn];
// fp16 weights
static __device__ __half g_Wqh[Dn*Dn];
static __device__ __half g_Wkh[Dn*Dn];
static __device__ __half g_Wvh[Dn*Dn];
static __device__ __half g_Woh[Dn*Dn];
static __device__ __half g_Wgeh[(size_t)En*HIDn*Dn];
static __device__ __half g_Wueh[(size_t)En*HIDn*Dn];
static __device__ __half g_Wdeh[(size_t)En*Dn*HIDn];
// routing
static __device__ int   g_cnt[En];
static __device__ int   g_cursor[En];
static __device__ int   g_rowtok[MAXROWS];
static __device__ int   g_rowexp[MAXROWS];
static __device__ float g_rowgate[MAXROWS];
static __device__ int   g_totalrows;
static __device__ float g_gsum[En];
static __device__ float g_psum[En];
static __device__ int   g_expid[Tn*2];
static __device__ float g_gateval[Tn*2];

// ======================= PTX helpers =========================================
static __device__ __forceinline__ uint32_t smem_u32_(const void* p){
    uint32_t a;
    asm("{ .reg .u64 t; cvta.to.shared.u64 t, %1; cvt.u32.u64 %0, t; }"
        : "=r"(a) : "l"(p));
    return a;
}

#define LDSM_X4(r0,r1,r2,r3,addr) \
    asm volatile("ldmatrix.sync.aligned.m8n8.x4.shared.b16 {%0,%1,%2,%3}, [%4];" \
        : "=r"(r0),"=r"(r1),"=r"(r2),"=r"(r3) : "r"(addr))

#define MMA16816(c,a,b) \
    asm volatile("mma.sync.aligned.m16n8k16.row.col.f32.f16.f16.f32 " \
        "{%0,%1,%2,%3}, {%4,%5,%6,%7}, {%8,%9}, {%0,%1,%2,%3};" \
        : "+f"((c)[0]),"+f"((c)[1]),"+f"((c)[2]),"+f"((c)[3]) \
        : "r"((a)[0]),"r"((a)[1]),"r"((a)[2]),"r"((a)[3]), \
          "r"((b)[0]),"r"((b)[1]))

#define CP_COMMIT() asm volatile("cp.async.commit_group;" ::: "memory")
#define CP_WAIT(N)  asm volatile("cp.async.wait_group %0;" :: "n"(N) : "memory")

static __device__ __forceinline__ void cp16_(uint32_t dst, const void* src, int srcsize){
    asm volatile("cp.async.cg.shared.global [%0], [%1], 16, %2;"
        :: "r"(dst), "l"((unsigned long long)__cvta_generic_to_global(src)),
           "r"(srcsize) : "memory");
}

// ============================== small kernels ================================
__global__ void k_reset() {
    int i = threadIdx.x;
    if (i < En) { g_cnt[i] = 0; g_gsum[i] = 0.f; g_psum[i] = 0.f; }
}

static __device__ __forceinline__ void f2h_one_(const float4* s, uint2* d, int i){
    float4 v = s[i];
    __half2 h0 = __floats2half2_rn(v.x, v.y);
    __half2 h1 = __floats2half2_rn(v.z, v.w);
    uint2 o;
    o.x = *reinterpret_cast<uint32_t*>(&h0);
    o.y = *reinterpret_cast<uint32_t*>(&h1);
    d[i] = o;
}

__global__ void k_f2h2(const float4* __restrict__ s0, const float4* __restrict__ s1,
                       uint2* __restrict__ d0, uint2* __restrict__ d1, int n4){
    int i = blockIdx.x*blockDim.x + threadIdx.x;
    if (i >= n4) return;
    if (blockIdx.y == 0) f2h_one_(s0, d0, i);
    else                 f2h_one_(s1, d1, i);
}

__global__ void k_f2h4(const float4* __restrict__ s0, const float4* __restrict__ s1,
                       const float4* __restrict__ s2p, const float4* __restrict__ s3,
                       uint2* __restrict__ d0, uint2* __restrict__ d1,
                       uint2* __restrict__ d2, uint2* __restrict__ d3, int n4){
    int i = blockIdx.x*blockDim.x + threadIdx.x;
    if (i >= n4) return;
    switch (blockIdx.y){
        case 0: f2h_one_(s0, d0, i); break;
        case 1: f2h_one_(s1, d1, i); break;
        case 2: f2h_one_(s2p, d2, i); break;
        default: f2h_one_(s3, d3, i); break;
    }
}

__global__ void k_f2h(const float4* __restrict__ s, uint2* __restrict__ d, int n4){
    int i = blockIdx.x*blockDim.x + threadIdx.x;
    if (i >= n4) return;
    f2h_one_(s, d, i);
}

__global__ void k_rmsnorm(const float* __restrict__ x, const float* __restrict__ w,
                          float* __restrict__ y, __half* __restrict__ yh) {
    int t = blockIdx.x;
    const float* xr = x + (size_t)t * Dn;
    int base = threadIdx.x * 4;
    float4 xv = *(const float4*)(xr + base);
    float ss = xv.x*xv.x + xv.y*xv.y + xv.z*xv.z + xv.w*xv.w;
    #pragma unroll
    for (int o = 16; o; o >>= 1) ss += __shfl_xor_sync(0xffffffffu, ss, o);
    __shared__ float ws[8];
    if ((threadIdx.x & 31) == 0) ws[threadIdx.x >> 5] = ss;
    __syncthreads();
    float tot = ws[0]+ws[1]+ws[2]+ws[3]+ws[4]+ws[5]+ws[6]+ws[7];
    float sc = rsqrtf(tot * (1.f/(float)Dn) + 1e-6f);
    float4 wv = *(const float4*)(w + base);
    float4 o4;
    o4.x = wv.x*xv.x*sc; o4.y = wv.y*xv.y*sc;
    o4.z = wv.z*xv.z*sc; o4.w = wv.w*xv.w*sc;
    if (y) *(float4*)(y + (size_t)t*Dn + base) = o4;
    __half2 h0 = __floats2half2_rn(o4.x, o4.y);
    __half2 h1 = __floats2half2_rn(o4.z, o4.w);
    uint2 ho;
    ho.x = *reinterpret_cast<uint32_t*>(&h0);
    ho.y = *reinterpret_cast<uint32_t*>(&h1);
    *(uint2*)(yh + (size_t)t*Dn + base) = ho;
}

// ===================== mma.sync GEMM (HMMA tensor path) ======================
#define EPI_PLAIN 0
#define EPI_RESID 1
#define EPI_DOWN  2
#define EPI_HALF  3
#define EPI_ROPE  4
#define GEMM_SMEM (3*32768)

template<int NITER, int EPI, bool GATHER, bool ESEL, bool ZSPLIT=false>
__global__ __launch_bounds__(256, 2)
void k_gemm(const __half* __restrict__ A0, int lda,
            const __half* __restrict__ B0, const __half* __restrict__ B1,
            const __half* __restrict__ B2,
            long bstride, int ldb,
            void* __restrict__ C0v, void* __restrict__ C1v, void* __restrict__ C2v,
            int ldc,
            const float* __restrict__ resid, float* __restrict__ Cdual)
{
    constexpr int S = 3;
    int mt = blockIdx.y, nt = blockIdx.x;
    if (ESEL && mt*128 >= g_totalrows) return;
    const __half* Bh = ZSPLIT ? B0
        : ((blockIdx.z==0) ? B0 : ((blockIdx.z==1) ? B1 : B2));
    void* Cv = ZSPLIT ? C0v
        : ((blockIdx.z==0) ? C0v : ((blockIdx.z==1) ? C1v : C2v));
    if (ESEL) Bh += (long)g_rowexp[mt*128] * bstride;
    long koff = ZSPLIT ? (long)blockIdx.z * (NITER*64) : 0;

    extern __shared__ __align__(128) char sm_[];
    uint32_t sbase = smem_u32_(sm_);

    int tid = threadIdx.x, lane = tid & 31, wid = tid >> 5;
    int warp_m = wid & 3, warp_n = wid >> 2;

    int lrow = tid >> 1;
    int lc0  = (tid & 1) * 4;
    const __half* asrc;
    bool avalid = true;
    if (GATHER){
        int tok = g_rowtok[mt*128 + lrow];
        avalid = (tok >= 0);
        asrc = A0 + (avalid ? (size_t)tok * lda : 0);
    } else {
        asrc = A0 + (size_t)(mt*128 + lrow) * lda;
    }
    asrc += koff;
    const __half* bsrc = Bh + (size_t)(nt*128 + lrow) * ldb + koff;
    int asz = avalid ? 16 : 0;
    uint32_t arow_s = sbase + lrow*128;
    uint32_t brow_s = arow_s + 16384;

    auto stg = [&](int it){
        int stage = it % S;
        uint32_t so = (uint32_t)stage * 32768u;
        const char* ag = (const char*)(asrc + it*64);
        const char* bg = (const char*)(bsrc + it*64);
        #pragma unroll
        for (int i = 0; i < 4; i++){
            int c = lc0 + i;
            uint32_t sw = (uint32_t)((c ^ (lrow & 7)) * 16);
            cp16_(arow_s + so + sw, ag + c*16, asz);
            cp16_(brow_s + so + sw, bg + c*16, 16);
        }
    };

    float acc[2][8][4];
    #pragma unroll
    for (int i=0;i<2;i++)
        #pragma unroll
        for (int j=0;j<8;j++)
            #pragma unroll
            for (int k=0;k<4;k++) acc[i][j][k]=0.f;

    #pragma unroll
    for (int it = 0; it < S-1; it++){ stg(it); CP_COMMIT(); }

    int a_rlo = (lane & 15);
    int a_chk = (lane >> 4);
    int b_rlo = (lane & 7) + ((lane & 16) ? 8 : 0);
    int b_chk = (lane >> 3) & 1;

    for (int it = 0; it < NITER; it++){
        CP_WAIT(S-2);
        __syncthreads();
        if (it + S-1 < NITER) stg(it + S-1);
        CP_COMMIT();

        uint32_t so = (uint32_t)(it % S) * 32768u;
        uint32_t abase = sbase + so;
        uint32_t bbase = abase + 16384;

        #pragma unroll
        for (int ks = 0; ks < 4; ks++){
            uint32_t a[2][4];
            #pragma unroll
            for (int mtile = 0; mtile < 2; mtile++){
                int row = warp_m*32 + mtile*16 + a_rlo;
                int chunk = 2*ks + a_chk;
                uint32_t addr = abase + row*128 + ((chunk ^ (row & 7)) * 16);
                LDSM_X4(a[mtile][0], a[mtile][1], a[mtile][2], a[mtile][3], addr);
            }
            uint32_t b[8][2];
            #pragma unroll
            for (int n2 = 0; n2 < 4; n2++){
                int row = warp_n*64 + n2*16 + b_rlo;
                int chunk = 2*ks + b_chk;
                uint32_t addr = bbase + row*128 + ((chunk ^ (row & 7)) * 16);
                uint32_t r0,r1,r2,r3;
                LDSM_X4(r0, r1, r2, r3, addr);
                b[2*n2][0]=r0; b[2*n2][1]=r1;
                b[2*n2+1][0]=r2; b[2*n2+1][1]=r3;
            }
            #pragma unroll
            for (int mtile = 0; mtile < 2; mtile++)
                #pragma unroll
                for (int n8 = 0; n8 < 8; n8++)
                    MMA16816(acc[mtile][n8], a[mtile], b[n8]);
        }
        __syncthreads();
    }

    // ---- epilogue ----
    int m0 = mt*128 + warp_m*32;
    int n0 = nt*128 + warp_n*64;
    int gq = lane >> 2, tq = lane & 3;
    #pragma unroll
    for (int mtile = 0; mtile < 2; mtile++){
        int r_lo = m0 + mtile*16 + gq;
        int r_hi = r_lo + 8;
        if (EPI == EPI_DOWN){
            float* C = (float*)Cv;
            int tok_lo = g_rowtok[r_lo], tok_hi = g_rowtok[r_hi];
            float gl = g_rowgate[r_lo], gh = g_rowgate[r_hi];
            #pragma unroll
            for (int n8 = 0; n8 < 8; n8++){
                int col = n0 + n8*8 + tq*2;
                if (tok_lo >= 0){
                    size_t o = (size_t)tok_lo*ldc + col;
                    atomicAdd(&C[o],   gl*acc[mtile][n8][0]);
                    atomicAdd(&C[o+1], gl*acc[mtile][n8][1]);
                }
                if (tok_hi >= 0){
                    size_t o = (size_t)tok_hi*ldc + col;
                    atomicAdd(&C[o],   gh*acc[mtile][n8][2]);
                    atomicAdd(&C[o+1], gh*acc[mtile][n8][3]);
                }
            }
        } else if (EPI == EPI_RESID){
            float* C = (float*)Cv;
            #pragma unroll
            for (int n8 = 0; n8 < 8; n8++){
                int col = n0 + n8*8 + tq*2;
                size_t o_lo = (size_t)r_lo*ldc + col;
                size_t o_hi = (size_t)r_hi*ldc + col;
                float2 rv0 = *(const float2*)(resid + o_lo);
                float2 rv1 = *(const float2*)(resid + o_hi);
                float2 v0, v1;
                v0.x = acc[mtile][n8][0] + rv0.x;
                v0.y = acc[mtile][n8][1] + rv0.y;
                v1.x = acc[mtile][n8][2] + rv1.x;
                v1.y = acc[mtile][n8][3] + rv1.y;
                *(float2*)(C + o_lo) = v0;
                *(float2*)(C + o_hi) = v1;
                *(float2*)(Cdual + o_lo) = v0;
                *(float2*)(Cdual + o_hi) = v1;
            }
        } else if (EPI == EPI_HALF){
            __half* Ch = (__half*)Cv;
            #pragma unroll
            for (int n8 = 0; n8 < 8; n8++){
                int col = n0 + n8*8 + tq*2;
                __half2 v0 = __floats2half2_rn(acc[mtile][n8][0], acc[mtile][n8][1]);
                __half2 v1 = __floats2half2_rn(acc[mtile][n8][2], acc[mtile][n8][3]);
                *(__half2*)(Ch + (size_t)r_lo*ldc + col) = v0;
                *(__half2*)(Ch + (size_t)r_hi*ldc + col) = v1;
            }
        } else if (EPI == EPI_ROPE){
            if (blockIdx.z == 2){
                // V: fp16 store
                __half* Ch = (__half*)Cv;
                #pragma unroll
                for (int n8 = 0; n8 < 8; n8++){
                    int col = n0 + n8*8 + tq*2;
                    __half2 v0 = __floats2half2_rn(acc[mtile][n8][0], acc[mtile][n8][1]);
                    __half2 v1 = __floats2half2_rn(acc[mtile][n8][2], acc[mtile][n8][3]);
                    *(__half2*)(Ch + (size_t)r_lo*ldc + col) = v0;
                    *(__half2*)(Ch + (size_t)r_hi*ldc + col) = v1;
                }
            } else {
                __half* Ch = (__half*)Cv;
                int s_lo = r_lo & (Sn-1);
                int s_hi = r_hi & (Sn-1);
                #pragma unroll
                for (int n8 = 0; n8 < 4; n8++){
                    int col = n0 + n8*8 + tq*2;
                    int i0 = col & 63;                      // < 32
                    float inv0 = powf(10000.f, (float)(-2*i0)   * (1.f/64.f));
                    float inv1 = powf(10000.f, (float)(-2*(i0+1)) * (1.f/64.f));
                    float c0l,s0l,c1l,s1l,c0h,s0h,c1h,s1h;
                    sincosf((float)s_lo*inv0, &s0l, &c0l);
                    sincosf((float)s_lo*inv1, &s1l, &c1l);
                    sincosf((float)s_hi*inv0, &s0h, &c0h);
                    sincosf((float)s_hi*inv1, &s1h, &c1h);
                    float a0 = acc[mtile][n8][0],   a1 = acc[mtile][n8][1];
                    float b0 = acc[mtile][n8+4][0], b1 = acc[mtile][n8+4][1];
                    float a2 = acc[mtile][n8][2],   a3 = acc[mtile][n8][3];
                    float b2 = acc[mtile][n8+4][2], b3 = acc[mtile][n8+4][3];
                    __half2 lo_a = __floats2half2_rn(a0*c0l - b0*s0l, a1*c1l - b1*s1l);
                    __half2 lo_b = __floats2half2_rn(b0*c0l + a0*s0l, b1*c1l + a1*s1l);
                    __half2 hi_a = __floats2half2_rn(a2*c0h - b2*s0h, a3*c1h - b3*s1h);
                    __half2 hi_b = __floats2half2_rn(b2*c0h + a2*s0h, b3*c1h + a3*s1h);
                    *(__half2*)(Ch + (size_t)r_lo*ldc + col)      = lo_a;
                    *(__half2*)(Ch + (size_t)r_lo*ldc + col + 32) = lo_b;
                    *(__half2*)(Ch + (size_t)r_hi*ldc + col)      = hi_a;
                    *(__half2*)(Ch + (size_t)r_hi*ldc + col + 32) = hi_b;
                }
            }
        } else {
            float* C = (float*)Cv;
            #pragma unroll
            for (int n8 = 0; n8 < 8; n8++){
                int col = n0 + n8*8 + tq*2;
                float2 v0, v1;
                v0.x = acc[mtile][n8][0]; v0.y = acc[mtile][n8][1];
                v1.x = acc[mtile][n8][2]; v1.y = acc[mtile][n8][3];
                *(float2*)(C + (size_t)r_lo*ldc + col) = v0;
                *(float2*)(C + (size_t)r_hi*ldc + col) = v1;
            }
        }
    }
}

// ===== V transpose: fp16 [t][h*64+d] -> fp16 Vt[bh][d][s], padded smem ======
// Row padded to 72 halves (144 B) so 16B vector stores stay aligned.
__global__ void k_vtrans(const __half* __restrict__ V, __half* __restrict__ Vt)
{
    __shared__ __align__(16) __half ts[64][72];
    int bh = blockIdx.x, st = blockIdx.y;
    int b = bh >> 4, h = bh & 15;
    int tid = threadIdx.x;                 // 128 threads
    int row = tid >> 1, c0 = (tid & 1) * 32;
    const uint4* src = (const uint4*)(V + ((size_t)(b*Sn + st*64 + row))*Dn
                                        + h*HDn + c0);
    #pragma unroll
    for (int i = 0; i < 4; i++){
        uint4 v = src[i];
        *(uint4*)&ts[row][c0 + 8*i] = v;
    }
    __syncthreads();
    __half* dst = Vt + ((size_t)bh*HDn + row)*Sn + st*64 + c0;
    #pragma unroll
    for (int i = 0; i < 32; i += 2){
        __half2 hv = __halves2half2(ts[c0+i][row], ts[c0+i+1][row]);
        *(__half2*)(dst + i) = hv;
    }
}

// ================= HMMA flash attention (m16n8k16) ===========================
__global__ __launch_bounds__(128)
void k_attn_mma(const __half* __restrict__ Qh, const __half* __restrict__ Kh,
                const __half* __restrict__ Vt, __half* __restrict__ O)
{
    __shared__ __align__(128) char sm[3*8192];
    uint32_t qs = smem_u32_(sm);
    uint32_t ks = qs + 8192;
    uint32_t vs = qs + 16384;

    int bh = blockIdx.x;
    int qt = gridDim.y - 1 - blockIdx.y;   // heavy tiles first
    int b = bh >> 4, h = bh & 15;
    int tid = threadIdx.x, lane = tid & 31, wid = tid >> 5;
    int q0 = qt*64;

    int srow = tid >> 1, sc0 = (tid & 1) * 4;
    int gq = lane >> 2, tq = lane & 3;
    int a_rlo = lane & 15, a_chk = lane >> 4;
    int b_rlo = (lane & 7) + ((lane & 16) ? 8 : 0);
    int b_chk = (lane >> 3) & 1;

    {
        const uint4* src = (const uint4*)(Qh + ((size_t)(b*Sn + q0 + srow))*Dn + h*HDn);
        #pragma unroll
        for (int i = 0; i < 4; i++){
            int c = sc0 + i;
            *(uint4*)(sm + srow*128 + ((c ^ (srow & 7)) * 16)) = src[c];
        }
    }
    __syncthreads();

    uint32_t qa[4][4];
    #pragma unroll
    for (int kc = 0; kc < 4; kc++){
        int row = wid*16 + a_rlo;
        int chunk = kc*2 + a_chk;
        uint32_t addr = qs + row*128 + ((chunk ^ (row & 7)) * 16);
        LDSM_X4(qa[kc][0], qa[kc][1], qa[kc][2], qa[kc][3], addr);
    }

    float o_[8][4];
    #pragma unroll
    for (int j=0;j<8;j++)
        #pragma unroll
        for (int k=0;k<4;k++) o_[j][k]=0.f;
    float m_lo = -1e30f, m_hi = -1e30f, l_lo = 0.f, l_hi = 0.f;

    for (int kt = 0; kt <= qt; kt++){
        {
            const uint4* ksrc = (const uint4*)(Kh + ((size_t)(b*Sn + kt*64 + srow))*Dn + h*HDn);
            const uint4* vsrc = (const uint4*)(Vt + ((size_t)bh*HDn + srow)*Sn + kt*64);
            #pragma unroll
            for (int i = 0; i < 4; i++){
                int c = sc0 + i;
                uint32_t sw = (uint32_t)((c ^ (srow & 7)) * 16);
                *(uint4*)(sm + 8192  + srow*128 + sw) = ksrc[c];
                *(uint4*)(sm + 16384 + srow*128 + sw) = vsrc[c];
            }
        }
        __syncthreads();

        float s_[8][4];
        #pragma unroll
        for (int j=0;j<8;j++)
            #pragma unroll
            for (int k=0;k<4;k++) s_[j][k]=0.f;
        #pragma unroll
        for (int kc = 0; kc < 4; kc++){
            uint32_t kb[8][2];
            #pragma unroll
            for (int n2 = 0; n2 < 4; n2++){
                int row = n2*16 + b_rlo;
                int chunk = kc*2 + b_chk;
                uint32_t addr = ks + row*128 + ((chunk ^ (row & 7)) * 16);
                uint32_t r0,r1,r2,r3;
                LDSM_X4(r0, r1, r2, r3, addr);
                kb[2*n2][0]=r0; kb[2*n2][1]=r1;
                kb[2*n2+1][0]=r2; kb[2*n2+1][1]=r3;
            }
            #pragma unroll
            for (int j = 0; j < 8; j++)
                MMA16816(s_[j], qa[kc], kb[j]);
        }

        int row_lo = q0 + wid*16 + gq;
        int row_hi = row_lo + 8;
        #pragma unroll
        for (int j = 0; j < 8; j++){
            int c0 = kt*64 + j*8 + tq*2;
            int c1 = c0 + 1;
            s_[j][0] = (c0 <= row_lo) ? s_[j][0]*0.125f : -1e30f;
            s_[j][1] = (c1 <= row_lo) ? s_[j][1]*0.125f : -1e30f;
            s_[j][2] = (c0 <= row_hi) ? s_[j][2]*0.125f : -1e30f;
            s_[j][3] = (c1 <= row_hi) ? s_[j][3]*0.125f : -1e30f;
        }

        float tm_lo = -1e30f, tm_hi = -1e30f;
        #pragma unroll
        for (int j = 0; j < 8; j++){
            tm_lo = fmaxf(tm_lo, fmaxf(s_[j][0], s_[j][1]));
            tm_hi = fmaxf(tm_hi, fmaxf(s_[j][2], s_[j][3]));
        }
        tm_lo = fmaxf(tm_lo, __shfl_xor_sync(0xffffffffu, tm_lo, 1));
        tm_lo = fmaxf(tm_lo, __shfl_xor_sync(0xffffffffu, tm_lo, 2));
        tm_hi = fmaxf(tm_hi, __shfl_xor_sync(0xffffffffu, tm_hi, 1));
        tm_hi = fmaxf(tm_hi, __shfl_xor_sync(0xffffffffu, tm_hi, 2));
        float mn_lo = fmaxf(m_lo, tm_lo);
        float mn_hi = fmaxf(m_hi, tm_hi);
        float corr_lo = __expf(m_lo - mn_lo);
        float corr_hi = __expf(m_hi - mn_hi);
        float rs_lo = 0.f, rs_hi = 0.f;
        #pragma unroll
        for (int j = 0; j < 8; j++){
            s_[j][0] = __expf(s_[j][0] - mn_lo);
            s_[j][1] = __expf(s_[j][1] - mn_lo);
            s_[j][2] = __expf(s_[j][2] - mn_hi);
            s_[j][3] = __expf(s_[j][3] - mn_hi);
            rs_lo += s_[j][0] + s_[j][1];
            rs_hi += s_[j][2] + s_[j][3];
        }
        rs_lo += __shfl_xor_sync(0xffffffffu, rs_lo, 1);
        rs_lo += __shfl_xor_sync(0xffffffffu, rs_lo, 2);
        rs_hi += __shfl_xor_sync(0xffffffffu, rs_hi, 1);
        rs_hi += __shfl_xor_sync(0xffffffffu, rs_hi, 2);
        l_lo = l_lo*corr_lo + rs_lo;
        l_hi = l_hi*corr_hi + rs_hi;
        m_lo = mn_lo; m_hi = mn_hi;
        #pragma unroll
        for (int j = 0; j < 8; j++){
            o_[j][0] *= corr_lo; o_[j][1] *= corr_lo;
            o_[j][2] *= corr_hi; o_[j][3] *= corr_hi;
        }

        uint32_t pa[4][4];
        #pragma unroll
        for (int kc = 0; kc < 4; kc++){
            __half2 h0 = __floats2half2_rn(s_[2*kc][0],   s_[2*kc][1]);
            __half2 h1 = __floats2half2_rn(s_[2*kc][2],   s_[2*kc][3]);
            __half2 h2 = __floats2half2_rn(s_[2*kc+1][0], s_[2*kc+1][1]);
            __half2 h3 = __floats2half2_rn(s_[2*kc+1][2], s_[2*kc+1][3]);
            pa[kc][0] = *reinterpret_cast<uint32_t*>(&h0);
            pa[kc][1] = *reinterpret_cast<uint32_t*>(&h1);
            pa[kc][2] = *reinterpret_cast<uint32_t*>(&h2);
            pa[kc][3] = *reinterpret_cast<uint32_t*>(&h3);
        }

        #pragma unroll
        for (int kc = 0; kc < 4; kc++){
            uint32_t vb[8][2];
            #pragma unroll
            for (int n2 = 0; n2 < 4; n2++){
                int row = n2*16 + b_rlo;
                int chunk = kc*2 + b_chk;
                uint32_t addr = vs + row*128 + ((chunk ^ (row & 7)) * 16);
                uint32_t r0,r1,r2,r3;
                LDSM_X4(r0, r1, r2, r3, addr);
                vb[2*n2][0]=r0; vb[2*n2][1]=r1;
                vb[2*n2+1][0]=r2; vb[2*n2+1][1]=r3;
            }
            #pragma unroll
            for (int j = 0; j < 8; j++)
                MMA16816(o_[j], pa[kc], vb[j]);
        }
        __syncthreads();
    }

    float inv_lo = 1.f/l_lo, inv_hi = 1.f/l_hi;
    int row_lo = q0 + wid*16 + gq;
    int row_hi = row_lo + 8;
    #pragma unroll
    for (int j = 0; j < 8; j++){
        int col = j*8 + tq*2;
        __half2 v0 = __floats2half2_rn(o_[j][0]*inv_lo, o_[j][1]*inv_lo);
        __half2 v1 = __floats2half2_rn(o_[j][2]*inv_hi, o_[j][3]*inv_hi);
        *(__half2*)(O + ((size_t)(b*Sn + row_lo))*Dn + h*HDn + col) = v0;
        *(__half2*)(O + ((size_t)(b*Sn + row_hi))*Dn + h*HDn + col) = v1;
    }
}

// =============================== gating / MoE ================================
__global__ void k_gate(const float* __restrict__ xn, const float* __restrict__ gw)
{
    int t = blockIdx.x;
    int w = threadIdx.x >> 5, lane = threadIdx.x & 31;
    const float* xr = xn + (size_t)t * Dn;
    const float* gr = gw + (size_t)w * Dn;
    float acc = 0.f;
    for (int d = lane; d < Dn; d += 32) acc = fmaf(xr[d], gr[d], acc);
    #pragma unroll
    for (int o=16;o;o>>=1) acc += __shfl_xor_sync(0xffffffffu, acc, o);
    __shared__ float lg[En];
    if (lane == 0) lg[w] = acc;
    __syncthreads();
    if (threadIdx.x == 0){
        int i1 = 0;
        for (int e=1;e<En;e++) if (lg[e] > lg[i1]) i1 = e;
        int i2 = -1;
        for (int e=0;e<En;e++){
            if (e == i1) continue;
            if (i2 < 0 || lg[e] > lg[i2]) i2 = e;
        }
        float l1 = lg[i1], l2 = lg[i2];
        float e2 = expf(l2 - l1);
        float inv = 1.f/(1.f + e2);
        float gv1 = inv, gv2 = e2*inv;
        g_expid[t*2]   = i1; g_expid[t*2+1]   = i2;
        g_gateval[t*2] = gv1; g_gateval[t*2+1] = gv2;
        atomicAdd(&g_cnt[i1], 1); atomicAdd(&g_cnt[i2], 1);
        atomicAdd(&g_gsum[i1], gv1); atomicAdd(&g_gsum[i2], gv2);
        float mx = lg[0];
        for (int e=1;e<En;e++) mx = fmaxf(mx, lg[e]);
        float pe[En]; float se = 0.f;
        for (int e=0;e<En;e++){ pe[e] = expf(lg[e]-mx); se += pe[e]; }
        float pinv = 1.f/se;
        for (int e=0;e<En;e++) atomicAdd(&g_psum[e], pe[e]*pinv);
    }
}

// merged offsets + row-init + scatter (single block)
__global__ void k_route(float* __restrict__ out, int write_aux)
{
    __shared__ int soff[En+1];
    if (threadIdx.x == 0){
        int tot = 0;
        for (int e=0;e<En;e++){
            soff[e] = tot;
            g_cursor[e] = tot;
            tot += ((g_cnt[e] + 127) >> 7) << 7;
        }
        soff[En] = tot;
        g_totalrows = tot;
        if (write_aux){
            float sacc = 0.f;
            for (int e=0;e<En;e++) sacc += g_gsum[e]*g_psum[e];
            out[(size_t)Tn*Dn] = (float)En * sacc / ((float)Tn*(float)Tn);
        }
    }
    __syncthreads();
    int tot = soff[En];
    for (int r = threadIdx.x; r < tot; r += blockDim.x){
        int e = 0;
        while (e+1 < En && r >= soff[e+1]) e++;
        g_rowexp[r] = e;
        g_rowtok[r] = -1;
    }
    __syncthreads();
    for (int t = threadIdx.x; t < Tn; t += blockDim.x){
        #pragma unroll
        for (int k=0;k<2;k++){
            int e = g_expid[t*2+k];
            int pos = atomicAdd(&g_cursor[e], 1);
            g_rowtok[pos] = t;
            g_rowgate[pos] = g_gateval[t*2+k];
        }
    }
}

// H = silu(G) * U, fp16 in -> fp16 out
__global__ void k_silumul()
{
    size_t i4 = ((size_t)blockIdx.x*blockDim.x + threadIdx.x) * 4;
    size_t n = (size_t)g_totalrows * HIDn;
    if (i4 >= n) return;
    uint2 gp = *(uint2*)&g_GBh[i4];
    uint2 up = *(uint2*)&g_UBh[i4];
    __half2 g0 = *reinterpret_cast<__half2*>(&gp.x);
    __half2 g1 = *reinterpret_cast<__half2*>(&gp.y);
    __half2 u0 = *reinterpret_cast<__half2*>(&up.x);
    __half2 u1 = *reinterpret_cast<__half2*>(&up.y);
    float gx = __low2float(g0),  gy = __high2float(g0);
    float gz = __low2float(g1),  gw_ = __high2float(g1);
    float ux = __low2float(u0),  uy = __high2float(u0);
    float uz = __low2float(u1),  uw = __high2float(u1);
    float a = (gx / (1.f + __expf(-gx))) * ux;
    float b = (gy / (1.f + __expf(-gy))) * uy;
    float c = (gz / (1.f + __expf(-gz))) * uz;
    float d = (gw_ / (1.f + __expf(-gw_))) * uw;
    __half2 h0 = __floats2half2_rn(a, b);
    __half2 h1 = __floats2half2_rn(c, d);
    uint2 o;
    o.x = *reinterpret_cast<uint32_t*>(&h0);
    o.y = *reinterpret_cast<uint32_t*>(&h1);
    *(uint2*)&g_Hh[i4] = o;
}

// ---------------------------------------------------------------------------
extern "C" void kernel_launch(void* const* d_in, const int* in_sizes, int n_in,
                              void* d_out, int out_size)
{
    (void)in_sizes; (void)n_in;
    const float* x   = (const float*)d_in[0];
    const float* wq  = (const float*)d_in[1];
    const float* wk  = (const float*)d_in[2];
    const float* wv  = (const float*)d_in[3];
    const float* wo  = (const float*)d_in[4];
    const float* anw = (const float*)d_in[5];
    const float* fnw = (const float*)d_in[6];
    const float* gw  = (const float*)d_in[7];
    const float* wge = (const float*)d_in[8];
    const float* wue = (const float*)d_in[9];
    const float* wde = (const float*)d_in[10];
    float* out = (float*)d_out;

    float *pH,*pXN2;
    __half *pXNh,*pATTh,*pXN2h,*pHh,*pGh,*pUh,*pQhh,*pKhh,*pVt,*pVh;
    __half *pWqh,*pWkh,*pWvh,*pWoh,*pWgeh,*pWueh,*pWdeh;
    cudaGetSymbolAddress((void**)&pH,    g_Hb);
    cudaGetSymbolAddress((void**)&pXN2,  g_XN2);
    cudaGetSymbolAddress((void**)&pGh,   g_GBh);
    cudaGetSymbolAddress((void**)&pUh,   g_UBh);
    cudaGetSymbolAddress((void**)&pXNh,  g_XNh);
    cudaGetSymbolAddress((void**)&pATTh, g_ATTh);
    cudaGetSymbolAddress((void**)&pXN2h, g_XN2h);
    cudaGetSymbolAddress((void**)&pHh,   g_Hh);
    cudaGetSymbolAddress((void**)&pQhh,  g_Qh);
    cudaGetSymbolAddress((void**)&pKhh,  g_Kh);
    cudaGetSymbolAddress((void**)&pVt,   g_Vt);
    cudaGetSymbolAddress((void**)&pVh,   g_Vh);
    cudaGetSymbolAddress((void**)&pWqh,  g_Wqh);
    cudaGetSymbolAddress((void**)&pWkh,  g_Wkh);
    cudaGetSymbolAddress((void**)&pWvh,  g_Wvh);
    cudaGetSymbolAddress((void**)&pWoh,  g_Woh);
    cudaGetSymbolAddress((void**)&pWgeh, g_Wgeh);
    cudaGetSymbolAddress((void**)&pWueh, g_Wueh);
    cudaGetSymbolAddress((void**)&pWdeh, g_Wdeh);

    cudaFuncSetAttribute(k_gemm<16,EPI_ROPE,false,false>,
                         cudaFuncAttributeMaxDynamicSharedMemorySize, GEMM_SMEM);
    cudaFuncSetAttribute(k_gemm<16,EPI_RESID,false,false>,
                         cudaFuncAttributeMaxDynamicSharedMemorySize, GEMM_SMEM);
    cudaFuncSetAttribute(k_gemm<16,EPI_HALF,true,true>,
                         cudaFuncAttributeMaxDynamicSharedMemorySize, GEMM_SMEM);
    cudaFuncSetAttribute(k_gemm<32,EPI_DOWN,false,true,true>,
                         cudaFuncAttributeMaxDynamicSharedMemorySize, GEMM_SMEM);

    // side stream for ALL weight conversions, overlapped with main path
    static cudaStream_t s2 = nullptr;
    static cudaEvent_t evFork = nullptr, evJoin = nullptr, evJoinQKV = nullptr;
    if (!s2){
        cudaStreamCreateWithFlags(&s2, cudaStreamNonBlocking);
        cudaEventCreateWithFlags(&evFork, cudaEventDisableTiming);
        cudaEventCreateWithFlags(&evJoin, cudaEventDisableTiming);
        cudaEventCreateWithFlags(&evJoinQKV, cudaEventDisableTiming);
    }

    k_reset<<<1, 32>>>();

    // ---- fork: weight conversions on s2 (QKV/O first, then experts) ----
    cudaEventRecord(evFork, 0);
    cudaStreamWaitEvent(s2, evFork, 0);
    {
        int n4 = Dn*Dn/4, blk = 256, g1 = (n4+blk-1)/blk;
        k_f2h4<<<dim3(g1,4), blk, 0, s2>>>((const float4*)wq, (const float4*)wk,
                                           (const float4*)wv, (const float4*)wo,
                                           (uint2*)pWqh, (uint2*)pWkh,
                                           (uint2*)pWvh, (uint2*)pWoh, n4);
        cudaEventRecord(evJoinQKV, s2);
        int ne4 = En*HIDn*(Dn/4), g2 = (ne4+blk-1)/blk;
        k_f2h2<<<dim3(g2,2), blk, 0, s2>>>((const float4*)wge, (const float4*)wue,
                                           (uint2*)pWgeh, (uint2*)pWueh, ne4);
        k_f2h<<<g2, blk, 0, s2>>>((const float4*)wde, (uint2*)pWdeh, ne4);
    }
    cudaEventRecord(evJoin, s2);

    // ---- main stream: attention path (rmsnorm overlaps the conversions) ----
    k_rmsnorm<<<Tn, 256>>>(x, anw, nullptr, pXNh);

    cudaStreamWaitEvent(0, evJoinQKV, 0);

    // QKV GEMM with fused RoPE: Q/K -> fp16 (rotated), V -> fp16
    k_gemm<16,EPI_ROPE,false,false><<<dim3(8,16,3), 256, GEMM_SMEM>>>(
        pXNh, Dn, pWqh, pWkh, pWvh, 0, Dn, pQhh, pKhh, pVh, Dn, nullptr, nullptr);

    // V -> transposed fp16
    k_vtrans<<<dim3(Bn*NHn, Sn/64), 128>>>(pVh, pVt);

    // HMMA flash attention (heavy qt tiles first)
    k_attn_mma<<<dim3(Bn*NHn, Sn/64), 128>>>(pQhh, pKhh, pVt, pATTh);

    k_gemm<16,EPI_RESID,false,false><<<dim3(8,16,1), 256, GEMM_SMEM>>>(
        pATTh, Dn, pWoh, pWoh, pWoh, 0, Dn, pH, pH, pH, Dn, x, out);

    k_rmsnorm<<<Tn, 256>>>(pH, fnw, pXN2, pXN2h);

    k_gate<<<Tn, 256>>>(pXN2, gw);
    int write_aux = (out_size > Tn*Dn) ? 1 : 0;
    k_route<<<1, 256>>>(out, write_aux);

    // ---- join: expert GEMMs need the converted weights ----
    cudaStreamWaitEvent(0, evJoin, 0);

    k_gemm<16,EPI_HALF,true,true><<<dim3(32, MAXROWS/128, 2), 256, GEMM_SMEM>>>(
        pXN2h, Dn, pWgeh, pWueh, pWueh, (long)HIDn*Dn, Dn, pGh, pUh, pUh, HIDn,
        nullptr, nullptr);

    k_silumul<<<(MAXROWS*(HIDn/4))/256, 256>>>();

    // down GEMM: split-K x2 (atomics accumulate across splits)
    k_gemm<32,EPI_DOWN,false,true,true><<<dim3(8, MAXROWS/128, 2), 256, GEMM_SMEM>>>(
        pHh, HIDn, pWdeh, pWdeh, pWdeh, (long)Dn*HIDn, HIDn, out, out, out, Dn,
        nullptr, nullptr);
}

// round 17
// speedup vs baseline: 1.0647x; 1.0035x over previous
#include <cuda_runtime.h>
#include <cuda_fp16.h>
#include <math.h>
#include <stdint.h>

// Problem constants
#define Bn 2
#define Sn 1024
#define Dn 1024
#define NHn 16
#define HDn 64
#define En 8
#define HIDn 4096
#define Tn (Bn*Sn)          // 2048 tokens
#define MAXROWS 5248        // >= 4096 assignments + 8*127 padding, mult of 128

// ---------------- scratch (static device globals; no allocation) -------------
static __device__ __half g_XNh [Tn*Dn];
static __device__ __half g_Vh  [Tn*Dn];
static __device__ __half g_Qh  [Tn*Dn];
static __device__ __half g_Kh  [Tn*Dn];
static __device__ __half g_Vt  [(size_t)Bn*NHn*HDn*Sn];
static __device__ __half g_ATTh[Tn*Dn];
static __device__ float  g_Hb  [Tn*Dn];
static __device__ float  g_XN2 [Tn*Dn];
static __device__ __half g_XN2h[Tn*Dn];
static __device__ __half g_GBh [(size_t)MAXROWS*HIDn];
static __device__ __half g_UBh [(size_t)MAXROWS*HIDn];
static __device__ __half g_Hh  [(size_t)MAXROWS*HIDn];
// fp16 weights
static __device__ __half g_Wqh[Dn*Dn];
static __device__ __half g_Wkh[Dn*Dn];
static __device__ __half g_Wvh[Dn*Dn];
static __device__ __half g_Woh[Dn*Dn];
static __device__ __half g_Wgeh[(size_t)En*HIDn*Dn];
static __device__ __half g_Wueh[(size_t)En*HIDn*Dn];
static __device__ __half g_Wdeh[(size_t)En*Dn*HIDn];
// routing
static __device__ int   g_cnt[En];
static __device__ int   g_cursor[En];
static __device__ int   g_rowtok[MAXROWS];
static __device__ int   g_rowexp[MAXROWS];
static __device__ float g_rowgate[MAXROWS];
static __device__ int   g_totalrows;
static __device__ float g_gsum[En];
static __device__ float g_psum[En];
static __device__ int   g_expid[Tn*2];
static __device__ float g_gateval[Tn*2];

// ======================= PTX helpers =========================================
static __device__ __forceinline__ uint32_t smem_u32_(const void* p){
    uint32_t a;
    asm("{ .reg .u64 t; cvta.to.shared.u64 t, %1; cvt.u32.u64 %0, t; }"
        : "=r"(a) : "l"(p));
    return a;
}

#define LDSM_X4(r0,r1,r2,r3,addr) \
    asm volatile("ldmatrix.sync.aligned.m8n8.x4.shared.b16 {%0,%1,%2,%3}, [%4];" \
        : "=r"(r0),"=r"(r1),"=r"(r2),"=r"(r3) : "r"(addr))

#define MMA16816(c,a,b) \
    asm volatile("mma.sync.aligned.m16n8k16.row.col.f32.f16.f16.f32 " \
        "{%0,%1,%2,%3}, {%4,%5,%6,%7}, {%8,%9}, {%0,%1,%2,%3};" \
        : "+f"((c)[0]),"+f"((c)[1]),"+f"((c)[2]),"+f"((c)[3]) \
        : "r"((a)[0]),"r"((a)[1]),"r"((a)[2]),"r"((a)[3]), \
          "r"((b)[0]),"r"((b)[1]))

#define CP_COMMIT() asm volatile("cp.async.commit_group;" ::: "memory")
#define CP_WAIT(N)  asm volatile("cp.async.wait_group %0;" :: "n"(N) : "memory")

static __device__ __forceinline__ void cp16_(uint32_t dst, const void* src, int srcsize){
    asm volatile("cp.async.cg.shared.global [%0], [%1], 16, %2;"
        :: "r"(dst), "l"((unsigned long long)__cvta_generic_to_global(src)),
           "r"(srcsize) : "memory");
}

// ============================== small kernels ================================
__global__ void k_reset() {
    int i = threadIdx.x;
    if (i < En) { g_cnt[i] = 0; g_gsum[i] = 0.f; g_psum[i] = 0.f; }
}

static __device__ __forceinline__ void f2h_one_(const float4* s, uint2* d, int i){
    float4 v = s[i];
    __half2 h0 = __floats2half2_rn(v.x, v.y);
    __half2 h1 = __floats2half2_rn(v.z, v.w);
    uint2 o;
    o.x = *reinterpret_cast<uint32_t*>(&h0);
    o.y = *reinterpret_cast<uint32_t*>(&h1);
    d[i] = o;
}

__global__ void k_f2h2(const float4* __restrict__ s0, const float4* __restrict__ s1,
                       uint2* __restrict__ d0, uint2* __restrict__ d1, int n4){
    int i = blockIdx.x*blockDim.x + threadIdx.x;
    if (i >= n4) return;
    if (blockIdx.y == 0) f2h_one_(s0, d0, i);
    else                 f2h_one_(s1, d1, i);
}

__global__ void k_f2h4(const float4* __restrict__ s0, const float4* __restrict__ s1,
                       const float4* __restrict__ s2p, const float4* __restrict__ s3,
                       uint2* __restrict__ d0, uint2* __restrict__ d1,
                       uint2* __restrict__ d2, uint2* __restrict__ d3, int n4){
    int i = blockIdx.x*blockDim.x + threadIdx.x;
    if (i >= n4) return;
    switch (blockIdx.y){
        case 0: f2h_one_(s0, d0, i); break;
        case 1: f2h_one_(s1, d1, i); break;
        case 2: f2h_one_(s2p, d2, i); break;
        default: f2h_one_(s3, d3, i); break;
    }
}

__global__ void k_f2h(const float4* __restrict__ s, uint2* __restrict__ d, int n4){
    int i = blockIdx.x*blockDim.x + threadIdx.x;
    if (i >= n4) return;
    f2h_one_(s, d, i);
}

__global__ void k_rmsnorm(const float* __restrict__ x, const float* __restrict__ w,
                          float* __restrict__ y, __half* __restrict__ yh) {
    int t = blockIdx.x;
    const float* xr = x + (size_t)t * Dn;
    int base = threadIdx.x * 4;
    float4 xv = *(const float4*)(xr + base);
    float ss = xv.x*xv.x + xv.y*xv.y + xv.z*xv.z + xv.w*xv.w;
    #pragma unroll
    for (int o = 16; o; o >>= 1) ss += __shfl_xor_sync(0xffffffffu, ss, o);
    __shared__ float ws[8];
    if ((threadIdx.x & 31) == 0) ws[threadIdx.x >> 5] = ss;
    __syncthreads();
    float tot = ws[0]+ws[1]+ws[2]+ws[3]+ws[4]+ws[5]+ws[6]+ws[7];
    float sc = rsqrtf(tot * (1.f/(float)Dn) + 1e-6f);
    float4 wv = *(const float4*)(w + base);
    float4 o4;
    o4.x = wv.x*xv.x*sc; o4.y = wv.y*xv.y*sc;
    o4.z = wv.z*xv.z*sc; o4.w = wv.w*xv.w*sc;
    if (y) *(float4*)(y + (size_t)t*Dn + base) = o4;
    __half2 h0 = __floats2half2_rn(o4.x, o4.y);
    __half2 h1 = __floats2half2_rn(o4.z, o4.w);
    uint2 ho;
    ho.x = *reinterpret_cast<uint32_t*>(&h0);
    ho.y = *reinterpret_cast<uint32_t*>(&h1);
    *(uint2*)(yh + (size_t)t*Dn + base) = ho;
}

// ===================== mma.sync GEMM (HMMA tensor path) ======================
#define EPI_PLAIN 0
#define EPI_RESID 1
#define EPI_DOWN  2
#define EPI_HALF  3
#define EPI_ROPE  4
#define GEMM_SMEM (3*32768)

template<int NITER, int EPI, bool GATHER, bool ESEL, bool ZSPLIT=false>
__global__ __launch_bounds__(256, 2)
void k_gemm(const __half* __restrict__ A0, int lda,
            const __half* __restrict__ B0, const __half* __restrict__ B1,
            const __half* __restrict__ B2,
            long bstride, int ldb,
            void* __restrict__ C0v, void* __restrict__ C1v, void* __restrict__ C2v,
            int ldc,
            const float* __restrict__ resid, float* __restrict__ Cdual)
{
    constexpr int S = 3;
    int mt = blockIdx.y, nt = blockIdx.x;
    if (ESEL && mt*128 >= g_totalrows) return;
    const __half* Bh = ZSPLIT ? B0
        : ((blockIdx.z==0) ? B0 : ((blockIdx.z==1) ? B1 : B2));
    void* Cv = ZSPLIT ? C0v
        : ((blockIdx.z==0) ? C0v : ((blockIdx.z==1) ? C1v : C2v));
    if (ESEL) Bh += (long)g_rowexp[mt*128] * bstride;
    long koff = ZSPLIT ? (long)blockIdx.z * (NITER*64) : 0;

    extern __shared__ __align__(128) char sm_[];
    uint32_t sbase = smem_u32_(sm_);

    int tid = threadIdx.x, lane = tid & 31, wid = tid >> 5;
    int warp_m = wid & 3, warp_n = wid >> 2;

    int lrow = tid >> 1;
    int lc0  = (tid & 1) * 4;
    const __half* asrc;
    bool avalid = true;
    if (GATHER){
        int tok = g_rowtok[mt*128 + lrow];
        avalid = (tok >= 0);
        asrc = A0 + (avalid ? (size_t)tok * lda : 0);
    } else {
        asrc = A0 + (size_t)(mt*128 + lrow) * lda;
    }
    asrc += koff;
    const __half* bsrc = Bh + (size_t)(nt*128 + lrow) * ldb + koff;
    int asz = avalid ? 16 : 0;
    uint32_t arow_s = sbase + lrow*128;
    uint32_t brow_s = arow_s + 16384;

    auto stg = [&](int it){
        int stage = it % S;
        uint32_t so = (uint32_t)stage * 32768u;
        const char* ag = (const char*)(asrc + it*64);
        const char* bg = (const char*)(bsrc + it*64);
        #pragma unroll
        for (int i = 0; i < 4; i++){
            int c = lc0 + i;
            uint32_t sw = (uint32_t)((c ^ (lrow & 7)) * 16);
            cp16_(arow_s + so + sw, ag + c*16, asz);
            cp16_(brow_s + so + sw, bg + c*16, 16);
        }
    };

    float acc[2][8][4];
    #pragma unroll
    for (int i=0;i<2;i++)
        #pragma unroll
        for (int j=0;j<8;j++)
            #pragma unroll
            for (int k=0;k<4;k++) acc[i][j][k]=0.f;

    #pragma unroll
    for (int it = 0; it < S-1; it++){ stg(it); CP_COMMIT(); }

    int a_rlo = (lane & 15);
    int a_chk = (lane >> 4);
    int b_rlo = (lane & 7) + ((lane & 16) ? 8 : 0);
    int b_chk = (lane >> 3) & 1;

    for (int it = 0; it < NITER; it++){
        CP_WAIT(S-2);
        __syncthreads();
        if (it + S-1 < NITER) stg(it + S-1);
        CP_COMMIT();

        uint32_t so = (uint32_t)(it % S) * 32768u;
        uint32_t abase = sbase + so;
        uint32_t bbase = abase + 16384;

        #pragma unroll
        for (int ks = 0; ks < 4; ks++){
            uint32_t a[2][4];
            #pragma unroll
            for (int mtile = 0; mtile < 2; mtile++){
                int row = warp_m*32 + mtile*16 + a_rlo;
                int chunk = 2*ks + a_chk;
                uint32_t addr = abase + row*128 + ((chunk ^ (row & 7)) * 16);
                LDSM_X4(a[mtile][0], a[mtile][1], a[mtile][2], a[mtile][3], addr);
            }
            uint32_t b[8][2];
            #pragma unroll
            for (int n2 = 0; n2 < 4; n2++){
                int row = warp_n*64 + n2*16 + b_rlo;
                int chunk = 2*ks + b_chk;
                uint32_t addr = bbase + row*128 + ((chunk ^ (row & 7)) * 16);
                uint32_t r0,r1,r2,r3;
                LDSM_X4(r0, r1, r2, r3, addr);
                b[2*n2][0]=r0; b[2*n2][1]=r1;
                b[2*n2+1][0]=r2; b[2*n2+1][1]=r3;
            }
            #pragma unroll
            for (int mtile = 0; mtile < 2; mtile++)
                #pragma unroll
                for (int n8 = 0; n8 < 8; n8++)
                    MMA16816(acc[mtile][n8], a[mtile], b[n8]);
        }
        __syncthreads();
    }

    // ---- epilogue ----
    int m0 = mt*128 + warp_m*32;
    int n0 = nt*128 + warp_n*64;
    int gq = lane >> 2, tq = lane & 3;
    #pragma unroll
    for (int mtile = 0; mtile < 2; mtile++){
        int r_lo = m0 + mtile*16 + gq;
        int r_hi = r_lo + 8;
        if (EPI == EPI_DOWN){
            float* C = (float*)Cv;
            int tok_lo = g_rowtok[r_lo], tok_hi = g_rowtok[r_hi];
            float gl = g_rowgate[r_lo], gh = g_rowgate[r_hi];
            #pragma unroll
            for (int n8 = 0; n8 < 8; n8++){
                int col = n0 + n8*8 + tq*2;
                if (tok_lo >= 0){
                    size_t o = (size_t)tok_lo*ldc + col;
                    atomicAdd(&C[o],   gl*acc[mtile][n8][0]);
                    atomicAdd(&C[o+1], gl*acc[mtile][n8][1]);
                }
                if (tok_hi >= 0){
                    size_t o = (size_t)tok_hi*ldc + col;
                    atomicAdd(&C[o],   gh*acc[mtile][n8][2]);
                    atomicAdd(&C[o+1], gh*acc[mtile][n8][3]);
                }
            }
        } else if (EPI == EPI_RESID){
            float* C = (float*)Cv;
            #pragma unroll
            for (int n8 = 0; n8 < 8; n8++){
                int col = n0 + n8*8 + tq*2;
                size_t o_lo = (size_t)r_lo*ldc + col;
                size_t o_hi = (size_t)r_hi*ldc + col;
                float2 rv0 = *(const float2*)(resid + o_lo);
                float2 rv1 = *(const float2*)(resid + o_hi);
                float2 v0, v1;
                v0.x = acc[mtile][n8][0] + rv0.x;
                v0.y = acc[mtile][n8][1] + rv0.y;
                v1.x = acc[mtile][n8][2] + rv1.x;
                v1.y = acc[mtile][n8][3] + rv1.y;
                *(float2*)(C + o_lo) = v0;
                *(float2*)(C + o_hi) = v1;
                *(float2*)(Cdual + o_lo) = v0;
                *(float2*)(Cdual + o_hi) = v1;
            }
        } else if (EPI == EPI_HALF){
            __half* Ch = (__half*)Cv;
            #pragma unroll
            for (int n8 = 0; n8 < 8; n8++){
                int col = n0 + n8*8 + tq*2;
                __half2 v0 = __floats2half2_rn(acc[mtile][n8][0], acc[mtile][n8][1]);
                __half2 v1 = __floats2half2_rn(acc[mtile][n8][2], acc[mtile][n8][3]);
                *(__half2*)(Ch + (size_t)r_lo*ldc + col) = v0;
                *(__half2*)(Ch + (size_t)r_hi*ldc + col) = v1;
            }
        } else if (EPI == EPI_ROPE){
            if (blockIdx.z == 2){
                // V: fp16 store
                __half* Ch = (__half*)Cv;
                #pragma unroll
                for (int n8 = 0; n8 < 8; n8++){
                    int col = n0 + n8*8 + tq*2;
                    __half2 v0 = __floats2half2_rn(acc[mtile][n8][0], acc[mtile][n8][1]);
                    __half2 v1 = __floats2half2_rn(acc[mtile][n8][2], acc[mtile][n8][3]);
                    *(__half2*)(Ch + (size_t)r_lo*ldc + col) = v0;
                    *(__half2*)(Ch + (size_t)r_hi*ldc + col) = v1;
                }
            } else {
                __half* Ch = (__half*)Cv;
                int s_lo = r_lo & (Sn-1);
                int s_hi = r_hi & (Sn-1);
                #pragma unroll
                for (int n8 = 0; n8 < 4; n8++){
                    int col = n0 + n8*8 + tq*2;
                    int i0 = col & 63;                      // < 32
                    float inv0 = powf(10000.f, (float)(-2*i0)   * (1.f/64.f));
                    float inv1 = powf(10000.f, (float)(-2*(i0+1)) * (1.f/64.f));
                    float c0l,s0l,c1l,s1l,c0h,s0h,c1h,s1h;
                    sincosf((float)s_lo*inv0, &s0l, &c0l);
                    sincosf((float)s_lo*inv1, &s1l, &c1l);
                    sincosf((float)s_hi*inv0, &s0h, &c0h);
                    sincosf((float)s_hi*inv1, &s1h, &c1h);
                    float a0 = acc[mtile][n8][0],   a1 = acc[mtile][n8][1];
                    float b0 = acc[mtile][n8+4][0], b1 = acc[mtile][n8+4][1];
                    float a2 = acc[mtile][n8][2],   a3 = acc[mtile][n8][3];
                    float b2 = acc[mtile][n8+4][2], b3 = acc[mtile][n8+4][3];
                    __half2 lo_a = __floats2half2_rn(a0*c0l - b0*s0l, a1*c1l - b1*s1l);
                    __half2 lo_b = __floats2half2_rn(b0*c0l + a0*s0l, b1*c1l + a1*s1l);
                    __half2 hi_a = __floats2half2_rn(a2*c0h - b2*s0h, a3*c1h - b3*s1h);
                    __half2 hi_b = __floats2half2_rn(b2*c0h + a2*s0h, b3*c1h + a3*s1h);
                    *(__half2*)(Ch + (size_t)r_lo*ldc + col)      = lo_a;
                    *(__half2*)(Ch + (size_t)r_lo*ldc + col + 32) = lo_b;
                    *(__half2*)(Ch + (size_t)r_hi*ldc + col)      = hi_a;
                    *(__half2*)(Ch + (size_t)r_hi*ldc + col + 32) = hi_b;
                }
            }
        } else {
            float* C = (float*)Cv;
            #pragma unroll
            for (int n8 = 0; n8 < 8; n8++){
                int col = n0 + n8*8 + tq*2;
                float2 v0, v1;
                v0.x = acc[mtile][n8][0]; v0.y = acc[mtile][n8][1];
                v1.x = acc[mtile][n8][2]; v1.y = acc[mtile][n8][3];
                *(float2*)(C + (size_t)r_lo*ldc + col) = v0;
                *(float2*)(C + (size_t)r_hi*ldc + col) = v1;
            }
        }
    }
}

// ===== V transpose: fp16 [t][h*64+d] -> fp16 Vt[bh][d][s], padded smem ======
__global__ void k_vtrans(const __half* __restrict__ V, __half* __restrict__ Vt)
{
    __shared__ __align__(16) __half ts[64][72];
    int bh = blockIdx.x, st = blockIdx.y;
    int b = bh >> 4, h = bh & 15;
    int tid = threadIdx.x;                 // 128 threads
    int row = tid >> 1, c0 = (tid & 1) * 32;
    const uint4* src = (const uint4*)(V + ((size_t)(b*Sn + st*64 + row))*Dn
                                        + h*HDn + c0);
    #pragma unroll
    for (int i = 0; i < 4; i++){
        uint4 v = src[i];
        *(uint4*)&ts[row][c0 + 8*i] = v;
    }
    __syncthreads();
    __half* dst = Vt + ((size_t)bh*HDn + row)*Sn + st*64 + c0;
    #pragma unroll
    for (int i = 0; i < 32; i += 2){
        __half2 hv = __halves2half2(ts[c0+i][row], ts[c0+i+1][row]);
        *(__half2*)(dst + i) = hv;
    }
}

// ========== HMMA flash attention (m16n8k16), cp.async double-buffer =========
__global__ __launch_bounds__(128)
void k_attn_mma(const __half* __restrict__ Qh, const __half* __restrict__ Kh,
                const __half* __restrict__ Vt, __half* __restrict__ O)
{
    // layout: Q [0,8K) ; buf0: K [8K,16K) V [16K,24K) ; buf1: K [24K,32K) V [32K,40K)
    __shared__ __align__(128) char sm[5*8192];
    uint32_t qs = smem_u32_(sm);

    int bh = blockIdx.x;
    int qt = gridDim.y - 1 - blockIdx.y;   // heavy tiles first
    int b = bh >> 4, h = bh & 15;
    int tid = threadIdx.x, lane = tid & 31, wid = tid >> 5;
    int q0 = qt*64;

    int srow = tid >> 1, sc0 = (tid & 1) * 4;
    int gq = lane >> 2, tq = lane & 3;
    int a_rlo = lane & 15, a_chk = lane >> 4;
    int b_rlo = (lane & 7) + ((lane & 16) ? 8 : 0);
    int b_chk = (lane >> 3) & 1;

    uint32_t soff[4];
    #pragma unroll
    for (int i = 0; i < 4; i++){
        int c = sc0 + i;
        soff[i] = (uint32_t)(srow*128 + ((c ^ (srow & 7)) * 16));
    }

    // ---- stage Q + first K/V tile via cp.async (one group) ----
    {
        const char* qg = (const char*)(Qh + ((size_t)(b*Sn + q0 + srow))*Dn + h*HDn);
        #pragma unroll
        for (int i = 0; i < 4; i++)
            cp16_(qs + soff[i], qg + (sc0+i)*16, 16);
    }
    auto stg_kv = [&](int kt){
        uint32_t buf = (uint32_t)(kt & 1) * 16384u;
        const char* kg = (const char*)(Kh + ((size_t)(b*Sn + kt*64 + srow))*Dn + h*HDn);
        const char* vg = (const char*)(Vt + ((size_t)bh*HDn + srow)*Sn + kt*64);
        #pragma unroll
        for (int i = 0; i < 4; i++){
            cp16_(qs + 8192u  + buf + soff[i], kg + (sc0+i)*16, 16);
            cp16_(qs + 16384u + buf + soff[i], vg + (sc0+i)*16, 16);
        }
    };
    stg_kv(0);
    CP_COMMIT();
    CP_WAIT(0);
    __syncthreads();

    // ---- Q fragments (once) ----
    uint32_t qa[4][4];
    #pragma unroll
    for (int kc = 0; kc < 4; kc++){
        int row = wid*16 + a_rlo;
        int chunk = kc*2 + a_chk;
        uint32_t addr = qs + row*128 + ((chunk ^ (row & 7)) * 16);
        LDSM_X4(qa[kc][0], qa[kc][1], qa[kc][2], qa[kc][3], addr);
    }

    float o_[8][4];
    #pragma unroll
    for (int j=0;j<8;j++)
        #pragma unroll
        for (int k=0;k<4;k++) o_[j][k]=0.f;
    float m_lo = -1e30f, m_hi = -1e30f, l_lo = 0.f, l_hi = 0.f;

    for (int kt = 0; kt <= qt; kt++){
        if (kt){ CP_WAIT(0); __syncthreads(); }
        if (kt < qt){ stg_kv(kt + 1); CP_COMMIT(); }   // overlaps compute below

        uint32_t kbase = qs + 8192u  + (uint32_t)(kt & 1) * 16384u;
        uint32_t vbase = qs + 16384u + (uint32_t)(kt & 1) * 16384u;

        float s_[8][4];
        #pragma unroll
        for (int j=0;j<8;j++)
            #pragma unroll
            for (int k=0;k<4;k++) s_[j][k]=0.f;
        #pragma unroll
        for (int kc = 0; kc < 4; kc++){
            uint32_t kb[8][2];
            #pragma unroll
            for (int n2 = 0; n2 < 4; n2++){
                int row = n2*16 + b_rlo;
                int chunk = kc*2 + b_chk;
                uint32_t addr = kbase + row*128 + ((chunk ^ (row & 7)) * 16);
                uint32_t r0,r1,r2,r3;
                LDSM_X4(r0, r1, r2, r3, addr);
                kb[2*n2][0]=r0; kb[2*n2][1]=r1;
                kb[2*n2+1][0]=r2; kb[2*n2+1][1]=r3;
            }
            #pragma unroll
            for (int j = 0; j < 8; j++)
                MMA16816(s_[j], qa[kc], kb[j]);
        }

        int row_lo = q0 + wid*16 + gq;
        int row_hi = row_lo + 8;
        #pragma unroll
        for (int j = 0; j < 8; j++){
            int c0 = kt*64 + j*8 + tq*2;
            int c1 = c0 + 1;
            s_[j][0] = (c0 <= row_lo) ? s_[j][0]*0.125f : -1e30f;
            s_[j][1] = (c1 <= row_lo) ? s_[j][1]*0.125f : -1e30f;
            s_[j][2] = (c0 <= row_hi) ? s_[j][2]*0.125f : -1e30f;
            s_[j][3] = (c1 <= row_hi) ? s_[j][3]*0.125f : -1e30f;
        }

        float tm_lo = -1e30f, tm_hi = -1e30f;
        #pragma unroll
        for (int j = 0; j < 8; j++){
            tm_lo = fmaxf(tm_lo, fmaxf(s_[j][0], s_[j][1]));
            tm_hi = fmaxf(tm_hi, fmaxf(s_[j][2], s_[j][3]));
        }
        tm_lo = fmaxf(tm_lo, __shfl_xor_sync(0xffffffffu, tm_lo, 1));
        tm_lo = fmaxf(tm_lo, __shfl_xor_sync(0xffffffffu, tm_lo, 2));
        tm_hi = fmaxf(tm_hi, __shfl_xor_sync(0xffffffffu, tm_hi, 1));
        tm_hi = fmaxf(tm_hi, __shfl_xor_sync(0xffffffffu, tm_hi, 2));
        float mn_lo = fmaxf(m_lo, tm_lo);
        float mn_hi = fmaxf(m_hi, tm_hi);
        float corr_lo = __expf(m_lo - mn_lo);
        float corr_hi = __expf(m_hi - mn_hi);
        float rs_lo = 0.f, rs_hi = 0.f;
        #pragma unroll
        for (int j = 0; j < 8; j++){
            s_[j][0] = __expf(s_[j][0] - mn_lo);
            s_[j][1] = __expf(s_[j][1] - mn_lo);
            s_[j][2] = __expf(s_[j][2] - mn_hi);
            s_[j][3] = __expf(s_[j][3] - mn_hi);
            rs_lo += s_[j][0] + s_[j][1];
            rs_hi += s_[j][2] + s_[j][3];
        }
        rs_lo += __shfl_xor_sync(0xffffffffu, rs_lo, 1);
        rs_lo += __shfl_xor_sync(0xffffffffu, rs_lo, 2);
        rs_hi += __shfl_xor_sync(0xffffffffu, rs_hi, 1);
        rs_hi += __shfl_xor_sync(0xffffffffu, rs_hi, 2);
        l_lo = l_lo*corr_lo + rs_lo;
        l_hi = l_hi*corr_hi + rs_hi;
        m_lo = mn_lo; m_hi = mn_hi;
        #pragma unroll
        for (int j = 0; j < 8; j++){
            o_[j][0] *= corr_lo; o_[j][1] *= corr_lo;
            o_[j][2] *= corr_hi; o_[j][3] *= corr_hi;
        }

        uint32_t pa[4][4];
        #pragma unroll
        for (int kc = 0; kc < 4; kc++){
            __half2 h0 = __floats2half2_rn(s_[2*kc][0],   s_[2*kc][1]);
            __half2 h1 = __floats2half2_rn(s_[2*kc][2],   s_[2*kc][3]);
            __half2 h2 = __floats2half2_rn(s_[2*kc+1][0], s_[2*kc+1][1]);
            __half2 h3 = __floats2half2_rn(s_[2*kc+1][2], s_[2*kc+1][3]);
            pa[kc][0] = *reinterpret_cast<uint32_t*>(&h0);
            pa[kc][1] = *reinterpret_cast<uint32_t*>(&h1);
            pa[kc][2] = *reinterpret_cast<uint32_t*>(&h2);
            pa[kc][3] = *reinterpret_cast<uint32_t*>(&h3);
        }

        #pragma unroll
        for (int kc = 0; kc < 4; kc++){
            uint32_t vb[8][2];
            #pragma unroll
            for (int n2 = 0; n2 < 4; n2++){
                int row = n2*16 + b_rlo;
                int chunk = kc*2 + b_chk;
                uint32_t addr = vbase + row*128 + ((chunk ^ (row & 7)) * 16);
                uint32_t r0,r1,r2,r3;
                LDSM_X4(r0, r1, r2, r3, addr);
                vb[2*n2][0]=r0; vb[2*n2][1]=r1;
                vb[2*n2+1][0]=r2; vb[2*n2+1][1]=r3;
            }
            #pragma unroll
            for (int j = 0; j < 8; j++)
                MMA16816(o_[j], pa[kc], vb[j]);
        }
    }

    float inv_lo = 1.f/l_lo, inv_hi = 1.f/l_hi;
    int row_lo = q0 + wid*16 + gq;
    int row_hi = row_lo + 8;
    #pragma unroll
    for (int j = 0; j < 8; j++){
        int col = j*8 + tq*2;
        __half2 v0 = __floats2half2_rn(o_[j][0]*inv_lo, o_[j][1]*inv_lo);
        __half2 v1 = __floats2half2_rn(o_[j][2]*inv_hi, o_[j][3]*inv_hi);
        *(__half2*)(O + ((size_t)(b*Sn + row_lo))*Dn + h*HDn + col) = v0;
        *(__half2*)(O + ((size_t)(b*Sn + row_hi))*Dn + h*HDn + col) = v1;
    }
}

// =============================== gating / MoE ================================
__global__ void k_gate(const float* __restrict__ xn, const float* __restrict__ gw)
{
    int t = blockIdx.x;
    int w = threadIdx.x >> 5, lane = threadIdx.x & 31;
    const float* xr = xn + (size_t)t * Dn;
    const float* gr = gw + (size_t)w * Dn;
    float acc = 0.f;
    for (int d = lane; d < Dn; d += 32) acc = fmaf(xr[d], gr[d], acc);
    #pragma unroll
    for (int o=16;o;o>>=1) acc += __shfl_xor_sync(0xffffffffu, acc, o);
    __shared__ float lg[En];
    if (lane == 0) lg[w] = acc;
    __syncthreads();
    if (threadIdx.x == 0){
        int i1 = 0;
        for (int e=1;e<En;e++) if (lg[e] > lg[i1]) i1 = e;
        int i2 = -1;
        for (int e=0;e<En;e++){
            if (e == i1) continue;
            if (i2 < 0 || lg[e] > lg[i2]) i2 = e;
        }
        float l1 = lg[i1], l2 = lg[i2];
        float e2 = expf(l2 - l1);
        float inv = 1.f/(1.f + e2);
        float gv1 = inv, gv2 = e2*inv;
        g_expid[t*2]   = i1; g_expid[t*2+1]   = i2;
        g_gateval[t*2] = gv1; g_gateval[t*2+1] = gv2;
        atomicAdd(&g_cnt[i1], 1); atomicAdd(&g_cnt[i2], 1);
        atomicAdd(&g_gsum[i1], gv1); atomicAdd(&g_gsum[i2], gv2);
        float mx = lg[0];
        for (int e=1;e<En;e++) mx = fmaxf(mx, lg[e]);
        float pe[En]; float se = 0.f;
        for (int e=0;e<En;e++){ pe[e] = expf(lg[e]-mx); se += pe[e]; }
        float pinv = 1.f/se;
        for (int e=0;e<En;e++) atomicAdd(&g_psum[e], pe[e]*pinv);
    }
}

// merged offsets + row-init + scatter (single block)
__global__ void k_route(float* __restrict__ out, int write_aux)
{
    __shared__ int soff[En+1];
    if (threadIdx.x == 0){
        int tot = 0;
        for (int e=0;e<En;e++){
            soff[e] = tot;
            g_cursor[e] = tot;
            tot += ((g_cnt[e] + 127) >> 7) << 7;
        }
        soff[En] = tot;
        g_totalrows = tot;
        if (write_aux){
            float sacc = 0.f;
            for (int e=0;e<En;e++) sacc += g_gsum[e]*g_psum[e];
            out[(size_t)Tn*Dn] = (float)En * sacc / ((float)Tn*(float)Tn);
        }
    }
    __syncthreads();
    int tot = soff[En];
    for (int r = threadIdx.x; r < tot; r += blockDim.x){
        int e = 0;
        while (e+1 < En && r >= soff[e+1]) e++;
        g_rowexp[r] = e;
        g_rowtok[r] = -1;
    }
    __syncthreads();
    for (int t = threadIdx.x; t < Tn; t += blockDim.x){
        #pragma unroll
        for (int k=0;k<2;k++){
            int e = g_expid[t*2+k];
            int pos = atomicAdd(&g_cursor[e], 1);
            g_rowtok[pos] = t;
            g_rowgate[pos] = g_gateval[t*2+k];
        }
    }
}

// H = silu(G) * U, fp16 in -> fp16 out
__global__ void k_silumul()
{
    size_t i4 = ((size_t)blockIdx.x*blockDim.x + threadIdx.x) * 4;
    size_t n = (size_t)g_totalrows * HIDn;
    if (i4 >= n) return;
    uint2 gp = *(uint2*)&g_GBh[i4];
    uint2 up = *(uint2*)&g_UBh[i4];
    __half2 g0 = *reinterpret_cast<__half2*>(&gp.x);
    __half2 g1 = *reinterpret_cast<__half2*>(&gp.y);
    __half2 u0 = *reinterpret_cast<__half2*>(&up.x);
    __half2 u1 = *reinterpret_cast<__half2*>(&up.y);
    float gx = __low2float(g0),  gy = __high2float(g0);
    float gz = __low2float(g1),  gw_ = __high2float(g1);
    float ux = __low2float(u0),  uy = __high2float(u0);
    float uz = __low2float(u1),  uw = __high2float(u1);
    float a = (gx / (1.f + __expf(-gx))) * ux;
    float b = (gy / (1.f + __expf(-gy))) * uy;
    float c = (gz / (1.f + __expf(-gz))) * uz;
    float d = (gw_ / (1.f + __expf(-gw_))) * uw;
    __half2 h0 = __floats2half2_rn(a, b);
    __half2 h1 = __floats2half2_rn(c, d);
    uint2 o;
    o.x = *reinterpret_cast<uint32_t*>(&h0);
    o.y = *reinterpret_cast<uint32_t*>(&h1);
    *(uint2*)&g_Hh[i4] = o;
}

// ---------------------------------------------------------------------------
extern "C" void kernel_launch(void* const* d_in, const int* in_sizes, int n_in,
                              void* d_out, int out_size)
{
    (void)in_sizes; (void)n_in;
    const float* x   = (const float*)d_in[0];
    const float* wq  = (const float*)d_in[1];
    const float* wk  = (const float*)d_in[2];
    const float* wv  = (const float*)d_in[3];
    const float* wo  = (const float*)d_in[4];
    const float* anw = (const float*)d_in[5];
    const float* fnw = (const float*)d_in[6];
    const float* gw  = (const float*)d_in[7];
    const float* wge = (const float*)d_in[8];
    const float* wue = (const float*)d_in[9];
    const float* wde = (const float*)d_in[10];
    float* out = (float*)d_out;

    float *pH,*pXN2;
    __half *pXNh,*pATTh,*pXN2h,*pHh,*pGh,*pUh,*pQhh,*pKhh,*pVt,*pVh;
    __half *pWqh,*pWkh,*pWvh,*pWoh,*pWgeh,*pWueh,*pWdeh;
    cudaGetSymbolAddress((void**)&pH,    g_Hb);
    cudaGetSymbolAddress((void**)&pXN2,  g_XN2);
    cudaGetSymbolAddress((void**)&pGh,   g_GBh);
    cudaGetSymbolAddress((void**)&pUh,   g_UBh);
    cudaGetSymbolAddress((void**)&pXNh,  g_XNh);
    cudaGetSymbolAddress((void**)&pATTh, g_ATTh);
    cudaGetSymbolAddress((void**)&pXN2h, g_XN2h);
    cudaGetSymbolAddress((void**)&pHh,   g_Hh);
    cudaGetSymbolAddress((void**)&pQhh,  g_Qh);
    cudaGetSymbolAddress((void**)&pKhh,  g_Kh);
    cudaGetSymbolAddress((void**)&pVt,   g_Vt);
    cudaGetSymbolAddress((void**)&pVh,   g_Vh);
    cudaGetSymbolAddress((void**)&pWqh,  g_Wqh);
    cudaGetSymbolAddress((void**)&pWkh,  g_Wkh);
    cudaGetSymbolAddress((void**)&pWvh,  g_Wvh);
    cudaGetSymbolAddress((void**)&pWoh,  g_Woh);
    cudaGetSymbolAddress((void**)&pWgeh, g_Wgeh);
    cudaGetSymbolAddress((void**)&pWueh, g_Wueh);
    cudaGetSymbolAddress((void**)&pWdeh, g_Wdeh);

    cudaFuncSetAttribute(k_gemm<16,EPI_ROPE,false,false>,
                         cudaFuncAttributeMaxDynamicSharedMemorySize, GEMM_SMEM);
    cudaFuncSetAttribute(k_gemm<16,EPI_RESID,false,false>,
                         cudaFuncAttributeMaxDynamicSharedMemorySize, GEMM_SMEM);
    cudaFuncSetAttribute(k_gemm<16,EPI_HALF,true,true>,
                         cudaFuncAttributeMaxDynamicSharedMemorySize, GEMM_SMEM);
    cudaFuncSetAttribute(k_gemm<32,EPI_DOWN,false,true,true>,
                         cudaFuncAttributeMaxDynamicSharedMemorySize, GEMM_SMEM);

    // side stream for ALL weight conversions, overlapped with main path
    static cudaStream_t s2 = nullptr;
    static cudaEvent_t evFork = nullptr, evJoin = nullptr, evJoinQKV = nullptr;
    if (!s2){
        cudaStreamCreateWithFlags(&s2, cudaStreamNonBlocking);
        cudaEventCreateWithFlags(&evFork, cudaEventDisableTiming);
        cudaEventCreateWithFlags(&evJoin, cudaEventDisableTiming);
        cudaEventCreateWithFlags(&evJoinQKV, cudaEventDisableTiming);
    }

    k_reset<<<1, 32>>>();

    // ---- fork: weight conversions on s2 (QKV/O first, then experts) ----
    cudaEventRecord(evFork, 0);
    cudaStreamWaitEvent(s2, evFork, 0);
    {
        int n4 = Dn*Dn/4, blk = 256, g1 = (n4+blk-1)/blk;
        k_f2h4<<<dim3(g1,4), blk, 0, s2>>>((const float4*)wq, (const float4*)wk,
                                           (const float4*)wv, (const float4*)wo,
                                           (uint2*)pWqh, (uint2*)pWkh,
                                           (uint2*)pWvh, (uint2*)pWoh, n4);
        cudaEventRecord(evJoinQKV, s2);
        int ne4 = En*HIDn*(Dn/4), g2 = (ne4+blk-1)/blk;
        k_f2h2<<<dim3(g2,2), blk, 0, s2>>>((const float4*)wge, (const float4*)wue,
                                           (uint2*)pWgeh, (uint2*)pWueh, ne4);
        k_f2h<<<g2, blk, 0, s2>>>((const float4*)wde, (uint2*)pWdeh, ne4);
    }
    cudaEventRecord(evJoin, s2);

    // ---- main stream: attention path (rmsnorm overlaps the conversions) ----
    k_rmsnorm<<<Tn, 256>>>(x, anw, nullptr, pXNh);

    cudaStreamWaitEvent(0, evJoinQKV, 0);

    // QKV GEMM with fused RoPE: Q/K -> fp16 (rotated), V -> fp16
    k_gemm<16,EPI_ROPE,false,false><<<dim3(8,16,3), 256, GEMM_SMEM>>>(
        pXNh, Dn, pWqh, pWkh, pWvh, 0, Dn, pQhh, pKhh, pVh, Dn, nullptr, nullptr);

    // V -> transposed fp16
    k_vtrans<<<dim3(Bn*NHn, Sn/64), 128>>>(pVh, pVt);

    // HMMA flash attention (heavy qt tiles first, cp.async double-buffered)
    k_attn_mma<<<dim3(Bn*NHn, Sn/64), 128>>>(pQhh, pKhh, pVt, pATTh);

    k_gemm<16,EPI_RESID,false,false><<<dim3(8,16,1), 256, GEMM_SMEM>>>(
        pATTh, Dn, pWoh, pWoh, pWoh, 0, Dn, pH, pH, pH, Dn, x, out);

    k_rmsnorm<<<Tn, 256>>>(pH, fnw, pXN2, pXN2h);

    k_gate<<<Tn, 256>>>(pXN2, gw);
    int write_aux = (out_size > Tn*Dn) ? 1 : 0;
    k_route<<<1, 256>>>(out, write_aux);

    // ---- join: expert GEMMs need the converted weights ----
    cudaStreamWaitEvent(0, evJoin, 0);

    k_gemm<16,EPI_HALF,true,true><<<dim3(32, MAXROWS/128, 2), 256, GEMM_SMEM>>>(
        pXN2h, Dn, pWgeh, pWueh, pWueh, (long)HIDn*Dn, Dn, pGh, pUh, pUh, HIDn,
        nullptr, nullptr);

    k_silumul<<<(MAXROWS*(HIDn/4))/256, 256>>>();

    // down GEMM: split-K x2 (atomics accumulate across splits)
    k_gemm<32,EPI_DOWN,false,true,true><<<dim3(8, MAXROWS/128, 2), 256, GEMM_SMEM>>>(
        pHh, HIDn, pWdeh, pWdeh, pWdeh, (long)Dn*HIDn, HIDn, out, out, out, Dn,
        nullptr, nullptr);
}